// round 15
// baseline (speedup 1.0000x reference)
#include <cuda_runtime.h>
#include <cuda_bf16.h>
#include <cuda_fp16.h>
#include <cstdint>
#include <math.h>

// ---------------- problem dims ----------------
constexpr int B_ = 32, L_ = 512, D_ = 256, H_ = 8, V_ = 4096, KC_ = 128;
constexpr int BL_ = B_ * L_;                 // 16384
constexpr long long BLD_ = (long long)BL_ * D_;   // 4194304
constexpr long long BLV_ = (long long)BL_ * V_;   // 67108864
constexpr int NTAB = B_ * KC_;               // 4096 distinct (b, idx) rows

// ---------------- fp32 scratch ----------------
constexpr long long OFF_DOT   = 0;                               // BL*128
constexpr long long OFF_G     = OFF_DOT + (long long)BL_ * KC_;
constexpr long long OFF_CG    = OFF_G + (long long)KC_ * D_;
constexpr long long OFF_WEV   = OFF_CG + (long long)B_ * D_;
constexpr long long OFF_WCT   = OFF_WEV + (long long)D_ * D_;
constexpr long long OFF_EN    = OFF_WCT + (long long)D_ * D_;
constexpr long long OFF_PART  = OFF_EN + KC_;
constexpr long long OFF_BQKV  = OFF_PART + BL_;
constexpr long long OFF_BZR   = OFF_BQKV + 1536;
constexpr long long OFF_PART2 = OFF_BZR + 256;                   // 32*8*256
constexpr long long SCRATCH_N = OFF_PART2 + 32LL * 8 * 256 + 64;

__device__ float d_scratch[SCRATCH_N];
__device__ int   d_idxbuf[BL_];

// CSR buffers: cnt[NTAB], offs[NTAB+1], cursor[NTAB], toklist[BL]
constexpr int CSR_CNT = 0;
constexpr int CSR_OFFS = NTAB;
constexpr int CSR_CUR = CSR_OFFS + NTAB + 1;
constexpr int CSR_TOK = CSR_CUR + NTAB;
constexpr int CSR_N = CSR_TOK + BL_ + 16;
__device__ int d_csr[CSR_N];

// ---------------- bf16 scratch ----------------
constexpr long long BF_X    = 0;                                // BLD
constexpr long long BF_WQ   = BF_X + BLD_;                      // 1536*256
constexpr long long BF_QKV  = BF_WQ + 1536LL * 256;             // BL*1536
constexpr long long BF_AP   = BF_QKV + (long long)BL_ * 1536;   // BL*512
constexpr long long BF_WZ   = BF_AP + (long long)BL_ * 512;     // 256*512
constexpr long long BF_N    = BF_WZ + 256LL * 512 + 64;

__device__ __nv_bfloat16 d_bf[BF_N];

// ---------------- fp16 scratch ----------------
constexpr long long HF_HW  = 0;                                 // V*D
constexpr long long HF_Y   = HF_HW + (long long)V_ * D_;        // NTAB*D
constexpr long long HF_Z   = HF_Y + (long long)NTAB * D_;       // BLD
constexpr long long HF_VQ  = HF_Z + BLD_;                       // KC*D
constexpr long long HF_N   = HF_VQ + (long long)KC_ * D_ + 64;

__device__ __half d_hf[HF_N];

// ==================== PTX helpers ====================
__device__ __forceinline__ uint32_t smem_u32(const void* p) {
    uint32_t a;
    asm("{ .reg .u64 t; cvta.to.shared.u64 t, %1; cvt.u32.u64 %0, t; }" : "=r"(a) : "l"(p));
    return a;
}
#define CP_ASYNC16(dst, src) \
    asm volatile("cp.async.cg.shared.global [%0], [%1], 16;" :: "r"(dst), "l"(src))
#define CP_COMMIT() asm volatile("cp.async.commit_group;" ::: "memory")
#define CP_WAIT(n)  asm volatile("cp.async.wait_group %0;" :: "n"(n) : "memory")
#define LDSM_X4(r, addr) \
    asm volatile("ldmatrix.sync.aligned.m8n8.x4.shared.b16 {%0,%1,%2,%3}, [%4];" \
                 : "=r"((r)[0]), "=r"((r)[1]), "=r"((r)[2]), "=r"((r)[3]) : "r"(addr))
#define LDSM_X4_T(r, addr) \
    asm volatile("ldmatrix.sync.aligned.m8n8.x4.trans.shared.b16 {%0,%1,%2,%3}, [%4];" \
                 : "=r"((r)[0]), "=r"((r)[1]), "=r"((r)[2]), "=r"((r)[3]) : "r"(addr))
#define MMA_BF16(d, a, b) \
    asm volatile("mma.sync.aligned.m16n8k16.row.col.f32.bf16.bf16.f32 " \
                 "{%0,%1,%2,%3}, {%4,%5,%6,%7}, {%8,%9}, {%0,%1,%2,%3};" \
                 : "+f"((d)[0]), "+f"((d)[1]), "+f"((d)[2]), "+f"((d)[3]) \
                 : "r"((a)[0]), "r"((a)[1]), "r"((a)[2]), "r"((a)[3]), \
                   "r"((b)[0]), "r"((b)[1]))
#define MMA_FP16(d, a, b) \
    asm volatile("mma.sync.aligned.m16n8k16.row.col.f32.f16.f16.f32 " \
                 "{%0,%1,%2,%3}, {%4,%5,%6,%7}, {%8,%9}, {%0,%1,%2,%3};" \
                 : "+f"((d)[0]), "+f"((d)[1]), "+f"((d)[2]), "+f"((d)[3]) \
                 : "r"((a)[0]), "r"((a)[1]), "r"((a)[2]), "r"((a)[3]), \
                   "r"((b)[0]), "r"((b)[1]))
// d.lo = lo, d.hi = hi
#define PACK_BF16X2(d, lo, hi) \
    asm("cvt.rn.bf16x2.f32 %0, %1, %2;" : "=r"(d) : "f"(hi), "f"(lo))
#define PACK_F16X2(d, lo, hi) \
    asm("cvt.rn.f16x2.f32 %0, %1, %2;" : "=r"(d) : "f"(hi), "f"(lo))
#define STG_CS_F2(ptr, v0, v1) \
    asm volatile("st.global.cs.v2.f32 [%0], {%1, %2};" :: "l"(ptr), "f"(v0), "f"(v1))

constexpr int LDT = 40;                         // padded row stride (16-bit elems)

// ==================== single-fp16 HMMA GEMM, 256x128 CTA tile, 512 threads ====================
constexpr int TS_A = 256 * LDT * 2;             // 20480
constexpr int TS_B = 128 * LDT * 2;             // 10240
constexpr int STAGES = TS_A + TS_B;             // 30720
constexpr int GS_SMEM = 3 * STAGES;             // 92160

// DOT GEMM (plain fp32 out, no bias)
__global__ __launch_bounds__(512, 1)
void gemmS(const __half* __restrict__ A, const __half* __restrict__ B,
           float* __restrict__ C, int N, int K) {
    extern __shared__ char smem[];
    const uint32_t sb = smem_u32(smem);
    const int tid = threadIdx.x, wid = tid >> 5, lane = tid & 31;
    const int m0 = blockIdx.y * 256, n0 = blockIdx.x * 128;
    const int mW = (wid & 7) * 32, nW = (wid >> 3) * 64;

    float acc[2][8][4];
#pragma unroll
    for (int i = 0; i < 2; i++)
#pragma unroll
        for (int j = 0; j < 8; j++)
#pragma unroll
            for (int c = 0; c < 4; c++) acc[i][j][c] = 0.f;

    auto load_stage = [&](int buf, int k0) {
        const uint32_t st = sb + buf * STAGES;
#pragma unroll
        for (int it = 0; it < 2; it++) {
            int c = it * 512 + tid;
            int row = c >> 2, cc = c & 3;
            CP_ASYNC16(st + (uint32_t)(row * LDT + cc * 8) * 2,
                       A + (size_t)(m0 + row) * K + k0 + cc * 8);
        }
        {
            int c = tid;
            int row = c >> 2, cc = c & 3;
            CP_ASYNC16(st + TS_A + (uint32_t)(row * LDT + cc * 8) * 2,
                       B + (size_t)(n0 + row) * K + k0 + cc * 8);
        }
        CP_COMMIT();
    };

    auto a_addr = [&](uint32_t base, int mBase, int k0) -> uint32_t {
        int t = lane >> 3;
        int r = mBase + ((t & 1) << 3) + (lane & 7);
        int c = k0 + ((t >> 1) << 3);
        return base + (uint32_t)(r * LDT + c) * 2;
    };
    auto b_addr = [&](uint32_t base, int nBase, int k0) -> uint32_t {
        int t = lane >> 3;
        int n = nBase + ((t >> 1) << 3) + (lane & 7);
        int c = k0 + ((t & 1) << 3);
        return base + (uint32_t)(n * LDT + c) * 2;
    };

    const int S = K >> 5;
    load_stage(0, 0);
    load_stage(1, 32);

    for (int s = 0; s < S; s++) {
        const int buf = s % 3;
        if (s + 1 < S) { CP_WAIT(1); } else { CP_WAIT(0); }
        __syncthreads();
        if (s + 2 < S) load_stage((s + 2) % 3, (s + 2) << 5);

        const uint32_t aS = sb + buf * STAGES;
        const uint32_t bS = aS + TS_A;

        uint32_t af[2][2][4];
#pragma unroll
        for (int kk = 0; kk < 2; kk++)
#pragma unroll
            for (int mf = 0; mf < 2; mf++)
                LDSM_X4(af[kk][mf], a_addr(aS, mW + mf * 16, kk * 16));

#pragma unroll
        for (int kk = 0; kk < 2; kk++) {
            const int k0 = kk * 16;
#pragma unroll
            for (int nf2 = 0; nf2 < 4; nf2++) {
                uint32_t r[4];
                LDSM_X4(r, b_addr(bS, nW + nf2 * 16, k0));
                uint32_t b01[2] = {r[0], r[1]}, b23[2] = {r[2], r[3]};
#pragma unroll
                for (int mf = 0; mf < 2; mf++) {
                    MMA_FP16(acc[mf][nf2 * 2], af[kk][mf], b01);
                    MMA_FP16(acc[mf][nf2 * 2 + 1], af[kk][mf], b23);
                }
            }
        }
    }
    __syncthreads();

    const int lr = lane >> 2, lc = (lane & 3) * 2;
#pragma unroll
    for (int mf = 0; mf < 2; mf++) {
        int row0 = m0 + mW + mf * 16 + lr;
#pragma unroll
        for (int nf = 0; nf < 8; nf++) {
            int col = n0 + nW + nf * 8 + lc;
            *reinterpret_cast<float2*>(C + (size_t)row0 * N + col) =
                make_float2(acc[mf][nf][0], acc[mf][nf][1]);
            *reinterpret_cast<float2*>(C + (size_t)(row0 + 8) * N + col) =
                make_float2(acc[mf][nf][2], acc[mf][nf][3]);
        }
    }
}

// Head GEMM with fused scatter: logits for tab row r written to every token in CSR[r].
__global__ __launch_bounds__(512, 1)
void gemmH(const __half* __restrict__ A, const __half* __restrict__ B,
           const float* __restrict__ bias, const int* __restrict__ offs,
           const int* __restrict__ toklist, float* __restrict__ out,
           int N, int K) {
    extern __shared__ char smem[];
    const uint32_t sb = smem_u32(smem);
    const int tid = threadIdx.x, wid = tid >> 5, lane = tid & 31;
    const int m0 = blockIdx.y * 256, n0 = blockIdx.x * 128;
    const int mW = (wid & 7) * 32, nW = (wid >> 3) * 64;

    float acc[2][8][4];
#pragma unroll
    for (int i = 0; i < 2; i++)
#pragma unroll
        for (int j = 0; j < 8; j++)
#pragma unroll
            for (int c = 0; c < 4; c++) acc[i][j][c] = 0.f;

    auto load_stage = [&](int buf, int k0) {
        const uint32_t st = sb + buf * STAGES;
#pragma unroll
        for (int it = 0; it < 2; it++) {
            int c = it * 512 + tid;
            int row = c >> 2, cc = c & 3;
            CP_ASYNC16(st + (uint32_t)(row * LDT + cc * 8) * 2,
                       A + (size_t)(m0 + row) * K + k0 + cc * 8);
        }
        {
            int c = tid;
            int row = c >> 2, cc = c & 3;
            CP_ASYNC16(st + TS_A + (uint32_t)(row * LDT + cc * 8) * 2,
                       B + (size_t)(n0 + row) * K + k0 + cc * 8);
        }
        CP_COMMIT();
    };

    auto a_addr = [&](uint32_t base, int mBase, int k0) -> uint32_t {
        int t = lane >> 3;
        int r = mBase + ((t & 1) << 3) + (lane & 7);
        int c = k0 + ((t >> 1) << 3);
        return base + (uint32_t)(r * LDT + c) * 2;
    };
    auto b_addr = [&](uint32_t base, int nBase, int k0) -> uint32_t {
        int t = lane >> 3;
        int n = nBase + ((t >> 1) << 3) + (lane & 7);
        int c = k0 + ((t & 1) << 3);
        return base + (uint32_t)(n * LDT + c) * 2;
    };

    const int S = K >> 5;
    load_stage(0, 0);
    load_stage(1, 32);

    for (int s = 0; s < S; s++) {
        const int buf = s % 3;
        if (s + 1 < S) { CP_WAIT(1); } else { CP_WAIT(0); }
        __syncthreads();
        if (s + 2 < S) load_stage((s + 2) % 3, (s + 2) << 5);

        const uint32_t aS = sb + buf * STAGES;
        const uint32_t bS = aS + TS_A;

        uint32_t af[2][2][4];
#pragma unroll
        for (int kk = 0; kk < 2; kk++)
#pragma unroll
            for (int mf = 0; mf < 2; mf++)
                LDSM_X4(af[kk][mf], a_addr(aS, mW + mf * 16, kk * 16));

#pragma unroll
        for (int kk = 0; kk < 2; kk++) {
            const int k0 = kk * 16;
#pragma unroll
            for (int nf2 = 0; nf2 < 4; nf2++) {
                uint32_t r[4];
                LDSM_X4(r, b_addr(bS, nW + nf2 * 16, k0));
                uint32_t b01[2] = {r[0], r[1]}, b23[2] = {r[2], r[3]};
#pragma unroll
                for (int mf = 0; mf < 2; mf++) {
                    MMA_FP16(acc[mf][nf2 * 2], af[kk][mf], b01);
                    MMA_FP16(acc[mf][nf2 * 2 + 1], af[kk][mf], b23);
                }
            }
        }
    }
    __syncthreads();

    const int lr = lane >> 2, lc = (lane & 3) * 2;
#pragma unroll
    for (int mf = 0; mf < 2; mf++) {
        int rowA = m0 + mW + mf * 16 + lr;
        int rowB = rowA + 8;
        int a0 = offs[rowA], a1 = offs[rowA + 1];
        int b0o = offs[rowB], b1o = offs[rowB + 1];
#pragma unroll
        for (int nf = 0; nf < 8; nf++) {
            int col = n0 + nW + nf * 8 + lc;
            float bb0 = bias[col], bb1 = bias[col + 1];
            float v00 = acc[mf][nf][0] + bb0, v01 = acc[mf][nf][1] + bb1;
            float v10 = acc[mf][nf][2] + bb0, v11 = acc[mf][nf][3] + bb1;
            for (int t = a0; t < a1; t++) {
                int tok = toklist[t];
                STG_CS_F2(out + ((size_t)tok << 12) + col, v00, v01);
            }
            for (int t = b0o; t < b1o; t++) {
                int tok = toklist[t];
                STG_CS_F2(out + ((size_t)tok << 12) + col, v10, v11);
            }
        }
    }
}

// ==================== single-bf16 HMMA GEMM (128x128, 2 CTA/SM) ====================
constexpr int TILE_B1 = 128 * LDT * 2;            // 10240
constexpr int STAGE_B1 = 2 * TILE_B1;             // 20480
constexpr int G1_SMEM = 3 * STAGE_B1;             // 61440

template<int OUTM>
__global__ __launch_bounds__(256, 2)
void gemm1(const __nv_bfloat16* __restrict__ A, const __nv_bfloat16* __restrict__ B,
           const float* __restrict__ bias, __nv_bfloat16* __restrict__ Ch,
           __half* __restrict__ Ch16, int N, int K) {
    extern __shared__ char smem[];
    const uint32_t sb = smem_u32(smem);
    const int tid = threadIdx.x, wid = tid >> 5, lane = tid & 31;
    const int m0 = blockIdx.y * 128, n0 = blockIdx.x * 128;
    const int warpM = wid & 1, warpN = wid >> 1;
    const int mW = warpM * 64, nW = warpN * 32;

    float acc[4][4][4];
#pragma unroll
    for (int i = 0; i < 4; i++)
#pragma unroll
        for (int j = 0; j < 4; j++)
#pragma unroll
            for (int c = 0; c < 4; c++) acc[i][j][c] = 0.f;

    auto load_stage = [&](int buf, int k0) {
#pragma unroll
        for (int mtx = 0; mtx < 2; mtx++) {
            const __nv_bfloat16* src = (mtx == 0) ? A : B;
            const int rbase = (mtx == 0) ? m0 : n0;
            uint32_t dst = sb + buf * STAGE_B1 + mtx * TILE_B1;
#pragma unroll
            for (int it = 0; it < 2; it++) {
                int c = it * 256 + tid;
                int row = c >> 2, cc = c & 3;
                CP_ASYNC16(dst + (uint32_t)(row * LDT + cc * 8) * 2,
                           src + (size_t)(rbase + row) * K + k0 + cc * 8);
            }
        }
        CP_COMMIT();
    };

    auto a_addr = [&](uint32_t base, int mBase, int k0) -> uint32_t {
        int t = lane >> 3;
        int r = mBase + ((t & 1) << 3) + (lane & 7);
        int c = k0 + ((t >> 1) << 3);
        return base + (uint32_t)(r * LDT + c) * 2;
    };
    auto b_addr = [&](uint32_t base, int nBase, int k0) -> uint32_t {
        int t = lane >> 3;
        int n = nBase + ((t >> 1) << 3) + (lane & 7);
        int c = k0 + ((t & 1) << 3);
        return base + (uint32_t)(n * LDT + c) * 2;
    };

    const int S = K >> 5;
    load_stage(0, 0);
    load_stage(1, 32);

    for (int s = 0; s < S; s++) {
        const int buf = s % 3;
        if (s + 1 < S) { CP_WAIT(1); } else { CP_WAIT(0); }
        __syncthreads();
        if (s + 2 < S) load_stage((s + 2) % 3, (s + 2) << 5);

        const uint32_t aB = sb + buf * STAGE_B1;
        const uint32_t bB = aB + TILE_B1;

        uint32_t af[2][4][4];
#pragma unroll
        for (int kk = 0; kk < 2; kk++)
#pragma unroll
            for (int mf = 0; mf < 4; mf++)
                LDSM_X4(af[kk][mf], a_addr(aB, mW + mf * 16, kk * 16));

#pragma unroll
        for (int kk = 0; kk < 2; kk++) {
            const int k0 = kk * 16;
#pragma unroll
            for (int nf2 = 0; nf2 < 2; nf2++) {
                uint32_t r[4];
                LDSM_X4(r, b_addr(bB, nW + nf2 * 16, k0));
                uint32_t b01[2] = {r[0], r[1]}, b23[2] = {r[2], r[3]};
#pragma unroll
                for (int mf = 0; mf < 4; mf++) {
                    MMA_BF16(acc[mf][nf2 * 2], af[kk][mf], b01);
                    MMA_BF16(acc[mf][nf2 * 2 + 1], af[kk][mf], b23);
                }
            }
        }
    }
    __syncthreads();

    const int lr = lane >> 2, lc = (lane & 3) * 2;
#pragma unroll
    for (int mf = 0; mf < 4; mf++) {
        int row0 = m0 + mW + mf * 16 + lr;
#pragma unroll
        for (int nf = 0; nf < 4; nf++) {
            int col = n0 + nW + nf * 8 + lc;
            float b0 = bias ? bias[col] : 0.f;
            float b1 = bias ? bias[col + 1] : 0.f;
#pragma unroll
            for (int half = 0; half < 2; half++) {
                size_t row = (size_t)(row0 + half * 8);
                float v0 = acc[mf][nf][half * 2] + b0;
                float v1 = acc[mf][nf][half * 2 + 1] + b1;
                if (OUTM == 0) {
                    uint32_t p; PACK_BF16X2(p, v0, v1);
                    *reinterpret_cast<uint32_t*>(Ch + row * N + col) = p;
                } else {
                    uint32_t ph; PACK_F16X2(ph, v0, v1);
                    *reinterpret_cast<uint32_t*>(Ch16 + row * N + col) = ph;
                }
            }
        }
    }
}

// ==================== bf16 HMMA flash attention, K/V resident ====================
constexpr int ALD = 72;
constexpr int AK_OFF = 0;
constexpr int AV_OFF = 512 * ALD * 2;
constexpr int AQ_OFF = AV_OFF + 512 * ALD * 2;
constexpr int ATT_SMEM = AQ_OFF + 128 * ALD * 2;   // 165888

__global__ __launch_bounds__(256, 1)
void attn_mma(const __nv_bfloat16* __restrict__ qkv, __nv_bfloat16* __restrict__ ap) {
    extern __shared__ char smem[];
    const uint32_t sKb = smem_u32(smem) + AK_OFF;
    const uint32_t sVb = smem_u32(smem) + AV_OFF;
    const uint32_t sQb = smem_u32(smem) + AQ_OFF;

    const int bid = blockIdx.x;
    const int h = bid & 7, b = bid >> 3;
    const int tid = threadIdx.x, wid = tid >> 5, lane = tid & 31;
    const size_t tok0 = (size_t)b * L_;
    const int hoff = h * 32;

#pragma unroll
    for (int i = 0; i < 16; i++) {
        int c = i * 256 + tid;
        int row = c >> 3, u = c & 7, seg = u >> 2, j = u & 3;
        CP_ASYNC16(sKb + (uint32_t)(row * ALD + seg * 32 + j * 8) * 2,
                   qkv + (tok0 + row) * 1536 + hoff + 512 + seg * 256 + j * 8);
    }
#pragma unroll
    for (int i = 0; i < 16; i++) {
        int c = i * 256 + tid;
        int row = c >> 3, u = c & 7, seg = u >> 2, j = u & 3;
        CP_ASYNC16(sVb + (uint32_t)(row * ALD + seg * 32 + j * 8) * 2,
                   qkv + (tok0 + row) * 1536 + hoff + 1024 + seg * 256 + j * 8);
    }
    CP_COMMIT();

    auto a_addr = [&](uint32_t base, int mBase, int k0) -> uint32_t {
        int t = lane >> 3;
        int r = mBase + ((t & 1) << 3) + (lane & 7);
        int c = k0 + ((t >> 1) << 3);
        return base + (uint32_t)(r * ALD + c) * 2;
    };
    auto b_addr = [&](uint32_t base, int nBase, int k0) -> uint32_t {
        int t = lane >> 3;
        int n = nBase + ((t >> 1) << 3) + (lane & 7);
        int c = k0 + ((t & 1) << 3);
        return base + (uint32_t)(n * ALD + c) * 2;
    };

    const float scale = 0.17677669529663687f;

    for (int qt = 0; qt < 4; qt++) {
#pragma unroll
        for (int i = 0; i < 4; i++) {
            int c = i * 256 + tid;
            int row = c >> 3, u = c & 7, seg = u >> 2, j = u & 3;
            uint4 v = *reinterpret_cast<const uint4*>(
                qkv + (tok0 + qt * 128 + row) * 1536 + hoff + seg * 256 + j * 8);
            *reinterpret_cast<uint4*>(reinterpret_cast<__nv_bfloat16*>(smem) +
                (AQ_OFF / 2) + row * ALD + seg * 32 + j * 8) = v;
        }
        if (qt == 0) CP_WAIT(0);
        __syncthreads();

        uint32_t aQ[4][4];
#pragma unroll
        for (int kf = 0; kf < 4; kf++) LDSM_X4(aQ[kf], a_addr(sQb, wid * 16, kf * 16));

        float O[8][4];
#pragma unroll
        for (int i = 0; i < 8; i++)
#pragma unroll
            for (int c = 0; c < 4; c++) O[i][c] = 0.f;
        float m0r = -1e30f, m1r = -1e30f, l0 = 0.f, l1 = 0.f;

#pragma unroll
        for (int kc = 0; kc < 4; kc++) {
            const uint32_t kChunk = sKb + (uint32_t)(kc * 128 * ALD) * 2;
            const uint32_t vChunk = sVb + (uint32_t)(kc * 128 * ALD) * 2;

            float S[16][4];
#pragma unroll
            for (int nf = 0; nf < 16; nf++)
#pragma unroll
                for (int c = 0; c < 4; c++) S[nf][c] = 0.f;
#pragma unroll
            for (int kf = 0; kf < 4; kf++) {
#pragma unroll
                for (int nf2 = 0; nf2 < 8; nf2++) {
                    uint32_t r[4];
                    LDSM_X4(r, b_addr(kChunk, nf2 * 16, kf * 16));
                    uint32_t b01[2] = {r[0], r[1]}, b23[2] = {r[2], r[3]};
                    MMA_BF16(S[nf2 * 2], aQ[kf], b01);
                    MMA_BF16(S[nf2 * 2 + 1], aQ[kf], b23);
                }
            }
            float mx0 = -1e30f, mx1 = -1e30f;
#pragma unroll
            for (int nf = 0; nf < 16; nf++) {
#pragma unroll
                for (int c = 0; c < 4; c++) S[nf][c] *= scale;
                mx0 = fmaxf(mx0, fmaxf(S[nf][0], S[nf][1]));
                mx1 = fmaxf(mx1, fmaxf(S[nf][2], S[nf][3]));
            }
            mx0 = fmaxf(mx0, __shfl_xor_sync(0xffffffffu, mx0, 1));
            mx0 = fmaxf(mx0, __shfl_xor_sync(0xffffffffu, mx0, 2));
            mx1 = fmaxf(mx1, __shfl_xor_sync(0xffffffffu, mx1, 1));
            mx1 = fmaxf(mx1, __shfl_xor_sync(0xffffffffu, mx1, 2));
            float mn0 = fmaxf(m0r, mx0), mn1 = fmaxf(m1r, mx1);
            float al0 = __expf(m0r - mn0), al1 = __expf(m1r - mn1);
            m0r = mn0; m1r = mn1;
            float rs0 = 0.f, rs1 = 0.f;
#pragma unroll
            for (int nf = 0; nf < 16; nf++) {
                S[nf][0] = __expf(S[nf][0] - mn0);
                S[nf][1] = __expf(S[nf][1] - mn0);
                S[nf][2] = __expf(S[nf][2] - mn1);
                S[nf][3] = __expf(S[nf][3] - mn1);
                rs0 += S[nf][0] + S[nf][1];
                rs1 += S[nf][2] + S[nf][3];
            }
            rs0 += __shfl_xor_sync(0xffffffffu, rs0, 1);
            rs0 += __shfl_xor_sync(0xffffffffu, rs0, 2);
            rs1 += __shfl_xor_sync(0xffffffffu, rs1, 1);
            rs1 += __shfl_xor_sync(0xffffffffu, rs1, 2);
            l0 = l0 * al0 + rs0;
            l1 = l1 * al1 + rs1;
#pragma unroll
            for (int i = 0; i < 8; i++) {
                O[i][0] *= al0; O[i][1] *= al0; O[i][2] *= al1; O[i][3] *= al1;
            }
#pragma unroll
            for (int t8 = 0; t8 < 8; t8++) {
                uint32_t pa[4];
                PACK_BF16X2(pa[0], S[2 * t8][0], S[2 * t8][1]);
                PACK_BF16X2(pa[1], S[2 * t8][2], S[2 * t8][3]);
                PACK_BF16X2(pa[2], S[2 * t8 + 1][0], S[2 * t8 + 1][1]);
                PACK_BF16X2(pa[3], S[2 * t8 + 1][2], S[2 * t8 + 1][3]);
#pragma unroll
                for (int vn2 = 0; vn2 < 4; vn2++) {
                    uint32_t r[4];
                    LDSM_X4_T(r, a_addr(vChunk, t8 * 16, vn2 * 16));
                    uint32_t b01[2] = {r[0], r[1]}, b23[2] = {r[2], r[3]};
                    MMA_BF16(O[vn2 * 2], pa, b01);
                    MMA_BF16(O[vn2 * 2 + 1], pa, b23);
                }
            }
        }

        float i0 = 1.f / l0, i1 = 1.f / l1;
        const int r = lane >> 2, cq = (lane & 3) * 2;
#pragma unroll
        for (int onf = 0; onf < 8; onf++) {
            int vc = onf * 8 + cq;
            int off = (vc < 32) ? (hoff + vc) : (256 + hoff + vc - 32);
#pragma unroll
            for (int half = 0; half < 2; half++) {
                size_t token = tok0 + qt * 128 + wid * 16 + r + half * 8;
                float inv = half ? i1 : i0;
                uint32_t p;
                PACK_BF16X2(p, O[onf][half * 2] * inv, O[onf][half * 2 + 1] * inv);
                *reinterpret_cast<uint32_t*>(ap + token * 512 + off) = p;
            }
        }
        __syncthreads();
    }
}

// ---------------- fp32 SGEMM: both gate tables in ONE launch ----------------
__global__ __launch_bounds__(256)
void gate_tabs_k(const float* __restrict__ vqe, const float* __restrict__ wev,
                 const float* __restrict__ ctx, const float* __restrict__ wct,
                 const float* __restrict__ gb, float* __restrict__ G,
                 float* __restrict__ Cg) {
    const bool isG = (blockIdx.y == 0);
    const float* A = isG ? vqe : ctx;
    const float* W = isG ? wev : wct;
    float* C = isG ? G : Cg;
    const int M = isG ? KC_ : B_;
    const int N = D_, K = D_;

    __shared__ float As[8][129];
    __shared__ float Ws[8][129];
    const int tid = threadIdx.x;
    const int tx = tid & 15, ty = tid >> 4;
    const int m0 = 0, n0 = blockIdx.x * 128;
    const int lm = tid >> 1, lh = tid & 1;

    float acc[8][8];
#pragma unroll
    for (int i = 0; i < 8; i++)
#pragma unroll
        for (int j = 0; j < 8; j++) acc[i][j] = 0.f;

    for (int k0 = 0; k0 < K; k0 += 8) {
        float4 av = make_float4(0.f, 0.f, 0.f, 0.f);
        float4 wv = make_float4(0.f, 0.f, 0.f, 0.f);
        int gm = m0 + lm;
        if (gm < M) av = *reinterpret_cast<const float4*>(A + (long long)gm * K + k0 + lh * 4);
        int gn = n0 + lm;
        if (gn < N) wv = *reinterpret_cast<const float4*>(W + (long long)gn * K + k0 + lh * 4);
        __syncthreads();
        As[lh * 4 + 0][lm] = av.x; As[lh * 4 + 1][lm] = av.y;
        As[lh * 4 + 2][lm] = av.z; As[lh * 4 + 3][lm] = av.w;
        Ws[lh * 4 + 0][lm] = wv.x; Ws[lh * 4 + 1][lm] = wv.y;
        Ws[lh * 4 + 2][lm] = wv.z; Ws[lh * 4 + 3][lm] = wv.w;
        __syncthreads();
#pragma unroll
        for (int kk = 0; kk < 8; kk++) {
            float ra[8], rw[8];
#pragma unroll
            for (int i = 0; i < 8; i++) ra[i] = As[kk][ty + 16 * i];
#pragma unroll
            for (int j = 0; j < 8; j++) rw[j] = Ws[kk][tx + 16 * j];
#pragma unroll
            for (int i = 0; i < 8; i++)
#pragma unroll
                for (int j = 0; j < 8; j++) acc[i][j] += ra[i] * rw[j];
        }
    }
#pragma unroll
    for (int i = 0; i < 8; i++) {
        int gm = m0 + ty + 16 * i;
        if (gm >= M) continue;
#pragma unroll
        for (int j = 0; j < 8; j++) {
            int gn = n0 + tx + 16 * j;
            if (gn >= N) continue;
            float v = acc[i][j];
            if (!isG) v += gb[gn];
            C[(long long)gm * N + gn] = v;
        }
    }
}

// ---------------- merged prep (also zeroes CSR cnt/cursor) ----------------
__global__ void prep_all_k(const float* __restrict__ abr, const float* __restrict__ abi,
                           const float* __restrict__ gw, const float* __restrict__ vqe,
                           const float* __restrict__ awr, const float* __restrict__ awi,
                           const float* __restrict__ hw, const int* __restrict__ tok,
                           const float* __restrict__ emb,
                           float* __restrict__ bq, float* __restrict__ bz,
                           float* __restrict__ en, float* __restrict__ wev,
                           float* __restrict__ wct,
                           __nv_bfloat16* __restrict__ wq, __nv_bfloat16* __restrict__ wz,
                           __half* __restrict__ vq16, __half* __restrict__ hw16,
                           __nv_bfloat16* __restrict__ x, int* __restrict__ csr) {
    int blk = blockIdx.x, t = threadIdx.x;
    if (blk < 264) {
        if (blk < 6) {
            int i = blk * 256 + t;
            int seg = i >> 8, j = i & 255, proj = seg >> 1;
            float r = abr[proj * 256 + j], i2 = abi[proj * 256 + j];
            bq[i] = ((seg & 1) == 0) ? (r - i2) : (r + i2);
        } else if (blk == 6) {
            bz[t] = abr[768 + t] - abi[768 + t];
        } else if (blk == 7) {
            if (t < KC_) {
                float a = 0.f;
                for (int d = 0; d < D_; d++) { float e = vqe[t * D_ + d]; a += e * e; }
                en[t] = a;
            }
        } else {
            int i = (blk - 8) * 256 + t;
            int d = i >> 8, j = i & 255;
            wev[i] = gw[d * 3 * D_ + 2 * j];
            wct[i] = gw[d * 3 * D_ + 2 * D_ + j];
        }
    } else if (blk < 1800) {
        long long i = (long long)(blk - 264) * 256 + t;
        int n = (int)(i >> 8), k = (int)(i & 255);
        int seg = n >> 8, j = n & 255, proj = seg >> 1;
        float v = ((seg & 1) == 0) ? awr[((long long)proj * 256 + j) * 256 + k]
                                   : awi[((long long)proj * 256 + j) * 256 + k];
        wq[i] = __float2bfloat16(v);
    } else if (blk < 2312) {
        long long i = (long long)(blk - 1800) * 256 + t;
        int n = (int)(i >> 9), k = (int)(i & 511);
        float v = (k < 256) ? awr[(768LL + n) * 256 + k] : -awi[(768LL + n) * 256 + (k - 256)];
        wz[i] = __float2bfloat16(v);
    } else if (blk < 2440) {
        long long i = (long long)(blk - 2312) * 256 + t;
        vq16[i] = __float2half(vqe[i]);
    } else if (blk < 6536) {
        long long i = (long long)(blk - 2440) * 256 + t;
        hw16[i] = __float2half(hw[i]);
    } else if (blk < 22920) {
        long long i = (long long)(blk - 6536) * 256 + t;
        int token = (int)(i >> 8), d = (int)(i & 255);
        x[i] = __float2bfloat16(emb[(long long)tok[token] * D_ + d]);
    } else {
        // zero cnt [0,NTAB) and cursor [CSR_CUR, CSR_CUR+NTAB): 32 blocks
        int i = (blk - 22920) * 256 + t;   // 0..8191
        if (i < NTAB) csr[CSR_CNT + i] = 0;
        else csr[CSR_CUR + (i - NTAB)] = 0;
    }
}

// ---------------- VQ argmin + loss + CSR count ----------------
__global__ void vq_argmin_k(const float* __restrict__ dot, const float* __restrict__ en,
                            const __half* __restrict__ Z16, const float* __restrict__ E,
                            int* __restrict__ idx_out, float* __restrict__ part,
                            int* __restrict__ cnt) {
    int tkn = blockIdx.x;
    int k = threadIdx.x;
    int wid = k >> 5, lane = k & 31;
    __shared__ float wv[4];
    __shared__ int wi[4];
    __shared__ float ws[4];

    float bv = en[k] - 2.f * dot[(long long)tkn * KC_ + k];
    int bi = k;
#pragma unroll
    for (int off = 16; off > 0; off >>= 1) {
        float ov = __shfl_xor_sync(0xffffffffu, bv, off);
        int oi = __shfl_xor_sync(0xffffffffu, bi, off);
        if (ov < bv || (ov == bv && oi < bi)) { bv = ov; bi = oi; }
    }
    if (lane == 0) { wv[wid] = bv; wi[wid] = bi; }
    __syncthreads();
    float fb = wv[0]; int fi = wi[0];
#pragma unroll
    for (int i = 1; i < 4; i++)
        if (wv[i] < fb || (wv[i] == fb && wi[i] < fi)) { fb = wv[i]; fi = wi[i]; }
    if (k == 0) {
        idx_out[tkn] = fi;
        atomicAdd(&cnt[(tkn >> 9) * KC_ + fi], 1);
    }

    float acc = 0.f;
#pragma unroll
    for (int d = k; d < D_; d += 128) {
        float diff = E[(long long)fi * D_ + d] - __half2float(Z16[(long long)tkn * 256 + d]);
        acc += diff * diff;
    }
#pragma unroll
    for (int off = 16; off > 0; off >>= 1) acc += __shfl_xor_sync(0xffffffffu, acc, off);
    if (lane == 0) ws[wid] = acc;
    __syncthreads();
    if (k == 0) part[tkn] = ws[0] + ws[1] + ws[2] + ws[3];
}

__global__ void vq_reduce_k(const float* __restrict__ part, float* __restrict__ out_loss) {
    __shared__ float s[256];
    float a = 0.f;
    for (int i = threadIdx.x; i < BL_; i += 256) a += part[i];
    s[threadIdx.x] = a;
    __syncthreads();
    for (int st = 128; st > 0; st >>= 1) {
        if (threadIdx.x < st) s[threadIdx.x] += s[threadIdx.x + st];
        __syncthreads();
    }
    if (threadIdx.x == 0) out_loss[0] = 2.f * s[0] / (float)BLD_;
}

// ---------------- CSR scan (1 block, 512 threads, 8 entries each) ----------------
__global__ __launch_bounds__(512)
void csr_scan_k(const int* __restrict__ cnt, int* __restrict__ offs) {
    __shared__ int s[512];
    int t = threadIdx.x;
    int base = t * 8;
    int local[8];
    int sum = 0;
#pragma unroll
    for (int i = 0; i < 8; i++) { local[i] = sum; sum += cnt[base + i]; }
    s[t] = sum;
    __syncthreads();
    for (int off = 1; off < 512; off <<= 1) {
        int v = (t >= off) ? s[t - off] : 0;
        __syncthreads();
        s[t] += v;
        __syncthreads();
    }
    int pre = (t == 0) ? 0 : s[t - 1];
#pragma unroll
    for (int i = 0; i < 8; i++) offs[base + i] = pre + local[i];
    if (t == 511) offs[NTAB] = s[511];
}

__global__ void csr_fill_k(const int* __restrict__ idx, const int* __restrict__ offs,
                           int* __restrict__ cursor, int* __restrict__ toklist) {
    int tok = blockIdx.x * 256 + threadIdx.x;
    int row = (tok >> 9) * KC_ + idx[tok];
    int pos = atomicAdd(&cursor[row], 1);
    toklist[offs[row] + pos] = tok;
}

// ---------------- stack partial (gate recomputed) ----------------
__global__ void gate_stack_k(const float* __restrict__ G, const float* __restrict__ Cg,
                             const int* __restrict__ idx, float* __restrict__ part2) {
    int b = blockIdx.x, p = blockIdx.y, d = threadIdx.x;
    float cg = Cg[b * D_ + d];
    float s = 0.f;
    int tbase = b * L_ + p * 64;
#pragma unroll 4
    for (int l = 0; l < 64; l++) {
        int tok = tbase + l;
        float x = G[(long long)idx[tok] * D_ + d] + cg;
        s += 1.f / (1.f + __expf(-x));
    }
    part2[((long long)b * 8 + p) * D_ + d] = s;
}

// ln+modrelu over the (b, codebook) TABLE; reduces part2 inline; kcode==0 rows
// also write the stack_top output (identical add order).
__global__ void ln_tab_k(const float* __restrict__ G, const float* __restrict__ Cg,
                         const float* __restrict__ part2,
                         const float* __restrict__ lg, const float* __restrict__ lb,
                         const float* __restrict__ ib, const float* __restrict__ mb,
                         __half* __restrict__ Ytab16, float* __restrict__ out_stk) {
    int row = blockIdx.x;            // b*128 + k
    int b = row >> 7, kcode = row & 127;
    int d = threadIdx.x;
    int wid = d >> 5, lane = d & 31;
    __shared__ float ws1[8], ws2[8];
    float stk = 0.f;
#pragma unroll
    for (int p = 0; p < 8; p++) stk += part2[((long long)b * 8 + p) * D_ + d];
    if (kcode == 0) out_stk[b * D_ + d] = stk;
    float gx = G[(long long)kcode * D_ + d] + Cg[b * D_ + d];
    float x = 1.f / (1.f + __expf(-gx)) + stk;
    float s1 = x, s2 = x * x;
#pragma unroll
    for (int off = 16; off > 0; off >>= 1) {
        s1 += __shfl_xor_sync(0xffffffffu, s1, off);
        s2 += __shfl_xor_sync(0xffffffffu, s2, off);
    }
    if (lane == 0) { ws1[wid] = s1; ws2[wid] = s2; }
    __syncthreads();
    float t1 = 0.f, t2 = 0.f;
#pragma unroll
    for (int i = 0; i < 8; i++) { t1 += ws1[i]; t2 += ws2[i]; }
    float mu = t1 * (1.f / 256.f);
    float var = t2 * (1.f / 256.f) - mu * mu;
    float nr = (x - mu) * rsqrtf(var + 1e-5f) * lg[d] + lb[d];
    float ni = ib[d];
    float mag = sqrtf(nr * nr + ni * ni);
    float sc = fmaxf(mag + mb[d], 0.f) / (mag + 1e-6f);
    Ytab16[(long long)row * D_ + d] = __float2half(nr * sc);
}

// ---------------- host launch ----------------
extern "C" void kernel_launch(void* const* d_in, const int* in_sizes, int n_in,
                              void* d_out, int out_size) {
    const int*   tokens = (const int*)d_in[0];
    const float* context = (const float*)d_in[1];
    const float* emb = (const float*)d_in[2];
    const float* awr = (const float*)d_in[3];
    const float* awi = (const float*)d_in[4];
    const float* abr = (const float*)d_in[5];
    const float* abi = (const float*)d_in[6];
    const float* vqe = (const float*)d_in[7];
    const float* gw  = (const float*)d_in[8];
    const float* gb  = (const float*)d_in[9];
    const float* lrg = (const float*)d_in[10];
    const float* lrb = (const float*)d_in[11];
    const float* lib = (const float*)d_in[13];
    const float* mrb = (const float*)d_in[14];
    const float* hw  = (const float*)d_in[15];
    const float* hb  = (const float*)d_in[16];
    float* out = (float*)d_out;

    float* S; cudaGetSymbolAddress((void**)&S, d_scratch);
    __nv_bfloat16* BF; cudaGetSymbolAddress((void**)&BF, d_bf);
    __half* HF; cudaGetSymbolAddress((void**)&HF, d_hf);
    int* idxb; cudaGetSymbolAddress((void**)&idxb, d_idxbuf);
    int* csr; cudaGetSymbolAddress((void**)&csr, d_csr);

    cudaFuncSetAttribute(gemmS, cudaFuncAttributeMaxDynamicSharedMemorySize, GS_SMEM);
    cudaFuncSetAttribute(gemmH, cudaFuncAttributeMaxDynamicSharedMemorySize, GS_SMEM);
    cudaFuncSetAttribute(gemm1<0>, cudaFuncAttributeMaxDynamicSharedMemorySize, G1_SMEM);
    cudaFuncSetAttribute(gemm1<1>, cudaFuncAttributeMaxDynamicSharedMemorySize, G1_SMEM);
    cudaFuncSetAttribute(attn_mma, cudaFuncAttributeMaxDynamicSharedMemorySize, ATT_SMEM);

    float* DOT   = S + OFF_DOT;
    float* G     = S + OFF_G;
    float* Cg    = S + OFF_CG;
    float* wev   = S + OFF_WEV;
    float* wct   = S + OFF_WCT;
    float* en    = S + OFF_EN;
    float* part  = S + OFF_PART;
    float* bqkv  = S + OFF_BQKV;
    float* bzr   = S + OFF_BZR;
    float* part2 = S + OFF_PART2;

    __nv_bfloat16* XBF  = BF + BF_X;
    __nv_bfloat16* WQBF = BF + BF_WQ;
    __nv_bfloat16* QKVB = BF + BF_QKV;
    __nv_bfloat16* APB  = BF + BF_AP;
    __nv_bfloat16* WZBF = BF + BF_WZ;

    __half* HW16 = HF + HF_HW;
    __half* Y16  = HF + HF_Y;
    __half* Z16  = HF + HF_Z;
    __half* VQ16 = HF + HF_VQ;

    prep_all_k<<<22952, 256>>>(abr, abi, gw, vqe, awr, awi, hw, tokens, emb,
                               bqkv, bzr, en, wev, wct,
                               WQBF, WZBF, VQ16, HW16, XBF, csr);

    // QKV GEMM (128x128, 2 CTA/SM) -> bf16 packed QKV
    gemm1<0><<<dim3(1536 / 128, BL_ / 128), 256, G1_SMEM>>>(
        XBF, WQBF, bqkv, QKVB, nullptr, 1536, 256);

    // flash attention (K/V resident per (b,h))
    attn_mma<<<B_ * H_, 256, ATT_SMEM>>>(QKVB, APB);

    // out clinear -> Z16 fp16 only
    gemm1<1><<<dim3(256 / 128, BL_ / 128), 256, G1_SMEM>>>(
        APB, WZBF, bzr, nullptr, Z16, 256, 512);

    // VQ dot + argmin (+ CSR count) + loss
    gemmS<<<dim3(1, BL_ / 256), 512, GS_SMEM>>>(Z16, VQ16, DOT, KC_, 256);
    vq_argmin_k<<<BL_, 128>>>(DOT, en, Z16, vqe, idxb, part, csr + CSR_CNT);
    vq_reduce_k<<<1, 256>>>(part, out + BLV_);

    // CSR offsets + fill
    csr_scan_k<<<1, 512>>>(csr + CSR_CNT, csr + CSR_OFFS);
    csr_fill_k<<<BL_ / 256, 256>>>(idxb, csr + CSR_OFFS, csr + CSR_CUR, csr + CSR_TOK);

    // gate tables (single launch)
    gate_tabs_k<<<dim3(2, 2), 256>>>(vqe, wev, context, wct, gb, G, Cg);

    // stack partials; ln_tab reduces part2 + writes stack_top output
    gate_stack_k<<<dim3(B_, 8), 256>>>(G, Cg, idxb, part2);
    ln_tab_k<<<NTAB, D_>>>(G, Cg, part2, lrg, lrb, lib, mrb, Y16, out + BLV_ + 1);

    // head GEMM with fused scatter: logits written directly per token
    gemmH<<<dim3(V_ / 128, NTAB / 256), 512, GS_SMEM>>>(
        Y16, HW16, hb, csr + CSR_OFFS, csr + CSR_TOK, out, V_, 256);
}

// round 16
// speedup vs baseline: 2.0271x; 2.0271x over previous
#include <cuda_runtime.h>
#include <cuda_bf16.h>
#include <cuda_fp16.h>
#include <cstdint>
#include <math.h>

// ---------------- problem dims ----------------
constexpr int B_ = 32, L_ = 512, D_ = 256, H_ = 8, V_ = 4096, KC_ = 128;
constexpr int BL_ = B_ * L_;                 // 16384
constexpr long long BLD_ = (long long)BL_ * D_;   // 4194304
constexpr long long BLV_ = (long long)BL_ * V_;   // 67108864
constexpr int NTAB = B_ * KC_;               // 4096 distinct (b, idx) rows

// ---------------- fp32 scratch ----------------
constexpr long long OFF_DOT   = 0;                               // BL*128
constexpr long long OFF_LT    = OFF_DOT + (long long)BL_ * KC_;  // NTAB*V
constexpr long long OFF_G     = OFF_LT + (long long)NTAB * V_;
constexpr long long OFF_CG    = OFF_G + (long long)KC_ * D_;
constexpr long long OFF_WEV   = OFF_CG + (long long)B_ * D_;
constexpr long long OFF_WCT   = OFF_WEV + (long long)D_ * D_;
constexpr long long OFF_EN    = OFF_WCT + (long long)D_ * D_;
constexpr long long OFF_PART  = OFF_EN + KC_;
constexpr long long OFF_BQKV  = OFF_PART + BL_;
constexpr long long OFF_BZR   = OFF_BQKV + 1536;
constexpr long long OFF_PART2 = OFF_BZR + 256;                   // 32*8*256
constexpr long long SCRATCH_N = OFF_PART2 + 32LL * 8 * 256 + 64;

__device__ float d_scratch[SCRATCH_N];
__device__ int   d_idxbuf[BL_];

// ---------------- bf16 scratch ----------------
constexpr long long BF_X    = 0;                                // BLD
constexpr long long BF_WQ   = BF_X + BLD_;                      // 1536*256
constexpr long long BF_QKV  = BF_WQ + 1536LL * 256;             // BL*1536
constexpr long long BF_AP   = BF_QKV + (long long)BL_ * 1536;   // BL*512
constexpr long long BF_WZ   = BF_AP + (long long)BL_ * 512;     // 256*512
constexpr long long BF_N    = BF_WZ + 256LL * 512 + 64;

__device__ __nv_bfloat16 d_bf[BF_N];

// ---------------- fp16 scratch ----------------
constexpr long long HF_HW  = 0;                                 // V*D
constexpr long long HF_Y   = HF_HW + (long long)V_ * D_;        // NTAB*D
constexpr long long HF_Z   = HF_Y + (long long)NTAB * D_;       // BLD
constexpr long long HF_VQ  = HF_Z + BLD_;                       // KC*D
constexpr long long HF_N   = HF_VQ + (long long)KC_ * D_ + 64;

__device__ __half d_hf[HF_N];

// ==================== PTX helpers ====================
__device__ __forceinline__ uint32_t smem_u32(const void* p) {
    uint32_t a;
    asm("{ .reg .u64 t; cvta.to.shared.u64 t, %1; cvt.u32.u64 %0, t; }" : "=r"(a) : "l"(p));
    return a;
}
#define CP_ASYNC16(dst, src) \
    asm volatile("cp.async.cg.shared.global [%0], [%1], 16;" :: "r"(dst), "l"(src))
#define CP_COMMIT() asm volatile("cp.async.commit_group;" ::: "memory")
#define CP_WAIT(n)  asm volatile("cp.async.wait_group %0;" :: "n"(n) : "memory")
#define LDSM_X4(r, addr) \
    asm volatile("ldmatrix.sync.aligned.m8n8.x4.shared.b16 {%0,%1,%2,%3}, [%4];" \
                 : "=r"((r)[0]), "=r"((r)[1]), "=r"((r)[2]), "=r"((r)[3]) : "r"(addr))
#define LDSM_X4_T(r, addr) \
    asm volatile("ldmatrix.sync.aligned.m8n8.x4.trans.shared.b16 {%0,%1,%2,%3}, [%4];" \
                 : "=r"((r)[0]), "=r"((r)[1]), "=r"((r)[2]), "=r"((r)[3]) : "r"(addr))
#define MMA_BF16(d, a, b) \
    asm volatile("mma.sync.aligned.m16n8k16.row.col.f32.bf16.bf16.f32 " \
                 "{%0,%1,%2,%3}, {%4,%5,%6,%7}, {%8,%9}, {%0,%1,%2,%3};" \
                 : "+f"((d)[0]), "+f"((d)[1]), "+f"((d)[2]), "+f"((d)[3]) \
                 : "r"((a)[0]), "r"((a)[1]), "r"((a)[2]), "r"((a)[3]), \
                   "r"((b)[0]), "r"((b)[1]))
#define MMA_FP16(d, a, b) \
    asm volatile("mma.sync.aligned.m16n8k16.row.col.f32.f16.f16.f32 " \
                 "{%0,%1,%2,%3}, {%4,%5,%6,%7}, {%8,%9}, {%0,%1,%2,%3};" \
                 : "+f"((d)[0]), "+f"((d)[1]), "+f"((d)[2]), "+f"((d)[3]) \
                 : "r"((a)[0]), "r"((a)[1]), "r"((a)[2]), "r"((a)[3]), \
                   "r"((b)[0]), "r"((b)[1]))
// d.lo = lo, d.hi = hi
#define PACK_BF16X2(d, lo, hi) \
    asm("cvt.rn.bf16x2.f32 %0, %1, %2;" : "=r"(d) : "f"(hi), "f"(lo))
#define PACK_F16X2(d, lo, hi) \
    asm("cvt.rn.f16x2.f32 %0, %1, %2;" : "=r"(d) : "f"(hi), "f"(lo))
#define STG_CS_F4(ptr, v) \
    asm volatile("st.global.cs.v4.f32 [%0], {%1, %2, %3, %4};" \
                 :: "l"(ptr), "f"((v).x), "f"((v).y), "f"((v).z), "f"((v).w))

constexpr int LDT = 40;                         // padded row stride (16-bit elems)

// ==================== single-fp16 HMMA GEMM, 256x128 CTA tile, 512 threads ====================
constexpr int TS_A = 256 * LDT * 2;             // 20480
constexpr int TS_B = 128 * LDT * 2;             // 10240
constexpr int STAGES = TS_A + TS_B;             // 30720
constexpr int GS_SMEM = 3 * STAGES;             // 92160

template<bool BIAS>
__global__ __launch_bounds__(512, 1)
void gemmS(const __half* __restrict__ A, const __half* __restrict__ B,
           const float* __restrict__ bias, float* __restrict__ C,
           int N, int K) {
    extern __shared__ char smem[];
    const uint32_t sb = smem_u32(smem);
    const int tid = threadIdx.x, wid = tid >> 5, lane = tid & 31;
    const int m0 = blockIdx.y * 256, n0 = blockIdx.x * 128;
    const int mW = (wid & 7) * 32, nW = (wid >> 3) * 64;

    float acc[2][8][4];
#pragma unroll
    for (int i = 0; i < 2; i++)
#pragma unroll
        for (int j = 0; j < 8; j++)
#pragma unroll
            for (int c = 0; c < 4; c++) acc[i][j][c] = 0.f;

    auto load_stage = [&](int buf, int k0) {
        const uint32_t st = sb + buf * STAGES;
#pragma unroll
        for (int it = 0; it < 2; it++) {
            int c = it * 512 + tid;
            int row = c >> 2, cc = c & 3;
            CP_ASYNC16(st + (uint32_t)(row * LDT + cc * 8) * 2,
                       A + (size_t)(m0 + row) * K + k0 + cc * 8);
        }
        {
            int c = tid;
            int row = c >> 2, cc = c & 3;
            CP_ASYNC16(st + TS_A + (uint32_t)(row * LDT + cc * 8) * 2,
                       B + (size_t)(n0 + row) * K + k0 + cc * 8);
        }
        CP_COMMIT();
    };

    auto a_addr = [&](uint32_t base, int mBase, int k0) -> uint32_t {
        int t = lane >> 3;
        int r = mBase + ((t & 1) << 3) + (lane & 7);
        int c = k0 + ((t >> 1) << 3);
        return base + (uint32_t)(r * LDT + c) * 2;
    };
    auto b_addr = [&](uint32_t base, int nBase, int k0) -> uint32_t {
        int t = lane >> 3;
        int n = nBase + ((t >> 1) << 3) + (lane & 7);
        int c = k0 + ((t & 1) << 3);
        return base + (uint32_t)(n * LDT + c) * 2;
    };

    const int S = K >> 5;
    load_stage(0, 0);
    load_stage(1, 32);

    for (int s = 0; s < S; s++) {
        const int buf = s % 3;
        if (s + 1 < S) { CP_WAIT(1); } else { CP_WAIT(0); }
        __syncthreads();
        if (s + 2 < S) load_stage((s + 2) % 3, (s + 2) << 5);

        const uint32_t aS = sb + buf * STAGES;
        const uint32_t bS = aS + TS_A;

        uint32_t af[2][2][4];
#pragma unroll
        for (int kk = 0; kk < 2; kk++)
#pragma unroll
            for (int mf = 0; mf < 2; mf++)
                LDSM_X4(af[kk][mf], a_addr(aS, mW + mf * 16, kk * 16));

#pragma unroll
        for (int kk = 0; kk < 2; kk++) {
            const int k0 = kk * 16;
#pragma unroll
            for (int nf2 = 0; nf2 < 4; nf2++) {
                uint32_t r[4];
                LDSM_X4(r, b_addr(bS, nW + nf2 * 16, k0));
                uint32_t b01[2] = {r[0], r[1]}, b23[2] = {r[2], r[3]};
#pragma unroll
                for (int mf = 0; mf < 2; mf++) {
                    MMA_FP16(acc[mf][nf2 * 2], af[kk][mf], b01);
                    MMA_FP16(acc[mf][nf2 * 2 + 1], af[kk][mf], b23);
                }
            }
        }
    }
    __syncthreads();

    const int lr = lane >> 2, lc = (lane & 3) * 2;
#pragma unroll
    for (int mf = 0; mf < 2; mf++) {
        int row0 = m0 + mW + mf * 16 + lr;
#pragma unroll
        for (int nf = 0; nf < 8; nf++) {
            int col = n0 + nW + nf * 8 + lc;
            float b0 = 0.f, b1 = 0.f;
            if (BIAS) { b0 = bias[col]; b1 = bias[col + 1]; }
            *reinterpret_cast<float2*>(C + (size_t)row0 * N + col) =
                make_float2(acc[mf][nf][0] + b0, acc[mf][nf][1] + b1);
            *reinterpret_cast<float2*>(C + (size_t)(row0 + 8) * N + col) =
                make_float2(acc[mf][nf][2] + b0, acc[mf][nf][3] + b1);
        }
    }
}

// ==================== single-bf16 HMMA GEMM (128x128, 2 CTA/SM) ====================
constexpr int TILE_B1 = 128 * LDT * 2;            // 10240
constexpr int STAGE_B1 = 2 * TILE_B1;             // 20480
constexpr int G1_SMEM = 3 * STAGE_B1;             // 61440

template<int OUTM>
__global__ __launch_bounds__(256, 2)
void gemm1(const __nv_bfloat16* __restrict__ A, const __nv_bfloat16* __restrict__ B,
           const float* __restrict__ bias, __nv_bfloat16* __restrict__ Ch,
           __half* __restrict__ Ch16, int N, int K) {
    extern __shared__ char smem[];
    const uint32_t sb = smem_u32(smem);
    const int tid = threadIdx.x, wid = tid >> 5, lane = tid & 31;
    const int m0 = blockIdx.y * 128, n0 = blockIdx.x * 128;
    const int warpM = wid & 1, warpN = wid >> 1;
    const int mW = warpM * 64, nW = warpN * 32;

    float acc[4][4][4];
#pragma unroll
    for (int i = 0; i < 4; i++)
#pragma unroll
        for (int j = 0; j < 4; j++)
#pragma unroll
            for (int c = 0; c < 4; c++) acc[i][j][c] = 0.f;

    auto load_stage = [&](int buf, int k0) {
#pragma unroll
        for (int mtx = 0; mtx < 2; mtx++) {
            const __nv_bfloat16* src = (mtx == 0) ? A : B;
            const int rbase = (mtx == 0) ? m0 : n0;
            uint32_t dst = sb + buf * STAGE_B1 + mtx * TILE_B1;
#pragma unroll
            for (int it = 0; it < 2; it++) {
                int c = it * 256 + tid;
                int row = c >> 2, cc = c & 3;
                CP_ASYNC16(dst + (uint32_t)(row * LDT + cc * 8) * 2,
                           src + (size_t)(rbase + row) * K + k0 + cc * 8);
            }
        }
        CP_COMMIT();
    };

    auto a_addr = [&](uint32_t base, int mBase, int k0) -> uint32_t {
        int t = lane >> 3;
        int r = mBase + ((t & 1) << 3) + (lane & 7);
        int c = k0 + ((t >> 1) << 3);
        return base + (uint32_t)(r * LDT + c) * 2;
    };
    auto b_addr = [&](uint32_t base, int nBase, int k0) -> uint32_t {
        int t = lane >> 3;
        int n = nBase + ((t >> 1) << 3) + (lane & 7);
        int c = k0 + ((t & 1) << 3);
        return base + (uint32_t)(n * LDT + c) * 2;
    };

    const int S = K >> 5;
    load_stage(0, 0);
    load_stage(1, 32);

    for (int s = 0; s < S; s++) {
        const int buf = s % 3;
        if (s + 1 < S) { CP_WAIT(1); } else { CP_WAIT(0); }
        __syncthreads();
        if (s + 2 < S) load_stage((s + 2) % 3, (s + 2) << 5);

        const uint32_t aB = sb + buf * STAGE_B1;
        const uint32_t bB = aB + TILE_B1;

        uint32_t af[2][4][4];
#pragma unroll
        for (int kk = 0; kk < 2; kk++)
#pragma unroll
            for (int mf = 0; mf < 4; mf++)
                LDSM_X4(af[kk][mf], a_addr(aB, mW + mf * 16, kk * 16));

#pragma unroll
        for (int kk = 0; kk < 2; kk++) {
            const int k0 = kk * 16;
#pragma unroll
            for (int nf2 = 0; nf2 < 2; nf2++) {
                uint32_t r[4];
                LDSM_X4(r, b_addr(bB, nW + nf2 * 16, k0));
                uint32_t b01[2] = {r[0], r[1]}, b23[2] = {r[2], r[3]};
#pragma unroll
                for (int mf = 0; mf < 4; mf++) {
                    MMA_BF16(acc[mf][nf2 * 2], af[kk][mf], b01);
                    MMA_BF16(acc[mf][nf2 * 2 + 1], af[kk][mf], b23);
                }
            }
        }
    }
    __syncthreads();

    const int lr = lane >> 2, lc = (lane & 3) * 2;
#pragma unroll
    for (int mf = 0; mf < 4; mf++) {
        int row0 = m0 + mW + mf * 16 + lr;
#pragma unroll
        for (int nf = 0; nf < 4; nf++) {
            int col = n0 + nW + nf * 8 + lc;
            float b0 = bias ? bias[col] : 0.f;
            float b1 = bias ? bias[col + 1] : 0.f;
#pragma unroll
            for (int half = 0; half < 2; half++) {
                size_t row = (size_t)(row0 + half * 8);
                float v0 = acc[mf][nf][half * 2] + b0;
                float v1 = acc[mf][nf][half * 2 + 1] + b1;
                if (OUTM == 0) {
                    uint32_t p; PACK_BF16X2(p, v0, v1);
                    *reinterpret_cast<uint32_t*>(Ch + row * N + col) = p;
                } else {
                    uint32_t ph; PACK_F16X2(ph, v0, v1);
                    *reinterpret_cast<uint32_t*>(Ch16 + row * N + col) = ph;
                }
            }
        }
    }
}

// ==================== bf16 HMMA flash attention, K/V resident ====================
constexpr int ALD = 72;
constexpr int AK_OFF = 0;
constexpr int AV_OFF = 512 * ALD * 2;
constexpr int AQ_OFF = AV_OFF + 512 * ALD * 2;
constexpr int ATT_SMEM = AQ_OFF + 128 * ALD * 2;   // 165888

__global__ __launch_bounds__(256, 1)
void attn_mma(const __nv_bfloat16* __restrict__ qkv, __nv_bfloat16* __restrict__ ap) {
    extern __shared__ char smem[];
    const uint32_t sKb = smem_u32(smem) + AK_OFF;
    const uint32_t sVb = smem_u32(smem) + AV_OFF;
    const uint32_t sQb = smem_u32(smem) + AQ_OFF;

    const int bid = blockIdx.x;
    const int h = bid & 7, b = bid >> 3;
    const int tid = threadIdx.x, wid = tid >> 5, lane = tid & 31;
    const size_t tok0 = (size_t)b * L_;
    const int hoff = h * 32;

#pragma unroll
    for (int i = 0; i < 16; i++) {
        int c = i * 256 + tid;
        int row = c >> 3, u = c & 7, seg = u >> 2, j = u & 3;
        CP_ASYNC16(sKb + (uint32_t)(row * ALD + seg * 32 + j * 8) * 2,
                   qkv + (tok0 + row) * 1536 + hoff + 512 + seg * 256 + j * 8);
    }
#pragma unroll
    for (int i = 0; i < 16; i++) {
        int c = i * 256 + tid;
        int row = c >> 3, u = c & 7, seg = u >> 2, j = u & 3;
        CP_ASYNC16(sVb + (uint32_t)(row * ALD + seg * 32 + j * 8) * 2,
                   qkv + (tok0 + row) * 1536 + hoff + 1024 + seg * 256 + j * 8);
    }
    CP_COMMIT();

    auto a_addr = [&](uint32_t base, int mBase, int k0) -> uint32_t {
        int t = lane >> 3;
        int r = mBase + ((t & 1) << 3) + (lane & 7);
        int c = k0 + ((t >> 1) << 3);
        return base + (uint32_t)(r * ALD + c) * 2;
    };
    auto b_addr = [&](uint32_t base, int nBase, int k0) -> uint32_t {
        int t = lane >> 3;
        int n = nBase + ((t >> 1) << 3) + (lane & 7);
        int c = k0 + ((t & 1) << 3);
        return base + (uint32_t)(n * ALD + c) * 2;
    };

    const float scale = 0.17677669529663687f;

    for (int qt = 0; qt < 4; qt++) {
#pragma unroll
        for (int i = 0; i < 4; i++) {
            int c = i * 256 + tid;
            int row = c >> 3, u = c & 7, seg = u >> 2, j = u & 3;
            uint4 v = *reinterpret_cast<const uint4*>(
                qkv + (tok0 + qt * 128 + row) * 1536 + hoff + seg * 256 + j * 8);
            *reinterpret_cast<uint4*>(reinterpret_cast<__nv_bfloat16*>(smem) +
                (AQ_OFF / 2) + row * ALD + seg * 32 + j * 8) = v;
        }
        if (qt == 0) CP_WAIT(0);
        __syncthreads();

        uint32_t aQ[4][4];
#pragma unroll
        for (int kf = 0; kf < 4; kf++) LDSM_X4(aQ[kf], a_addr(sQb, wid * 16, kf * 16));

        float O[8][4];
#pragma unroll
        for (int i = 0; i < 8; i++)
#pragma unroll
            for (int c = 0; c < 4; c++) O[i][c] = 0.f;
        float m0r = -1e30f, m1r = -1e30f, l0 = 0.f, l1 = 0.f;

#pragma unroll
        for (int kc = 0; kc < 4; kc++) {
            const uint32_t kChunk = sKb + (uint32_t)(kc * 128 * ALD) * 2;
            const uint32_t vChunk = sVb + (uint32_t)(kc * 128 * ALD) * 2;

            float S[16][4];
#pragma unroll
            for (int nf = 0; nf < 16; nf++)
#pragma unroll
                for (int c = 0; c < 4; c++) S[nf][c] = 0.f;
#pragma unroll
            for (int kf = 0; kf < 4; kf++) {
#pragma unroll
                for (int nf2 = 0; nf2 < 8; nf2++) {
                    uint32_t r[4];
                    LDSM_X4(r, b_addr(kChunk, nf2 * 16, kf * 16));
                    uint32_t b01[2] = {r[0], r[1]}, b23[2] = {r[2], r[3]};
                    MMA_BF16(S[nf2 * 2], aQ[kf], b01);
                    MMA_BF16(S[nf2 * 2 + 1], aQ[kf], b23);
                }
            }
            float mx0 = -1e30f, mx1 = -1e30f;
#pragma unroll
            for (int nf = 0; nf < 16; nf++) {
#pragma unroll
                for (int c = 0; c < 4; c++) S[nf][c] *= scale;
                mx0 = fmaxf(mx0, fmaxf(S[nf][0], S[nf][1]));
                mx1 = fmaxf(mx1, fmaxf(S[nf][2], S[nf][3]));
            }
            mx0 = fmaxf(mx0, __shfl_xor_sync(0xffffffffu, mx0, 1));
            mx0 = fmaxf(mx0, __shfl_xor_sync(0xffffffffu, mx0, 2));
            mx1 = fmaxf(mx1, __shfl_xor_sync(0xffffffffu, mx1, 1));
            mx1 = fmaxf(mx1, __shfl_xor_sync(0xffffffffu, mx1, 2));
            float mn0 = fmaxf(m0r, mx0), mn1 = fmaxf(m1r, mx1);
            float al0 = __expf(m0r - mn0), al1 = __expf(m1r - mn1);
            m0r = mn0; m1r = mn1;
            float rs0 = 0.f, rs1 = 0.f;
#pragma unroll
            for (int nf = 0; nf < 16; nf++) {
                S[nf][0] = __expf(S[nf][0] - mn0);
                S[nf][1] = __expf(S[nf][1] - mn0);
                S[nf][2] = __expf(S[nf][2] - mn1);
                S[nf][3] = __expf(S[nf][3] - mn1);
                rs0 += S[nf][0] + S[nf][1];
                rs1 += S[nf][2] + S[nf][3];
            }
            rs0 += __shfl_xor_sync(0xffffffffu, rs0, 1);
            rs0 += __shfl_xor_sync(0xffffffffu, rs0, 2);
            rs1 += __shfl_xor_sync(0xffffffffu, rs1, 1);
            rs1 += __shfl_xor_sync(0xffffffffu, rs1, 2);
            l0 = l0 * al0 + rs0;
            l1 = l1 * al1 + rs1;
#pragma unroll
            for (int i = 0; i < 8; i++) {
                O[i][0] *= al0; O[i][1] *= al0; O[i][2] *= al1; O[i][3] *= al1;
            }
#pragma unroll
            for (int t8 = 0; t8 < 8; t8++) {
                uint32_t pa[4];
                PACK_BF16X2(pa[0], S[2 * t8][0], S[2 * t8][1]);
                PACK_BF16X2(pa[1], S[2 * t8][2], S[2 * t8][3]);
                PACK_BF16X2(pa[2], S[2 * t8 + 1][0], S[2 * t8 + 1][1]);
                PACK_BF16X2(pa[3], S[2 * t8 + 1][2], S[2 * t8 + 1][3]);
#pragma unroll
                for (int vn2 = 0; vn2 < 4; vn2++) {
                    uint32_t r[4];
                    LDSM_X4_T(r, a_addr(vChunk, t8 * 16, vn2 * 16));
                    uint32_t b01[2] = {r[0], r[1]}, b23[2] = {r[2], r[3]};
                    MMA_BF16(O[vn2 * 2], pa, b01);
                    MMA_BF16(O[vn2 * 2 + 1], pa, b23);
                }
            }
        }

        float i0 = 1.f / l0, i1 = 1.f / l1;
        const int r = lane >> 2, cq = (lane & 3) * 2;
#pragma unroll
        for (int onf = 0; onf < 8; onf++) {
            int vc = onf * 8 + cq;
            int off = (vc < 32) ? (hoff + vc) : (256 + hoff + vc - 32);
#pragma unroll
            for (int half = 0; half < 2; half++) {
                size_t token = tok0 + qt * 128 + wid * 16 + r + half * 8;
                float inv = half ? i1 : i0;
                uint32_t p;
                PACK_BF16X2(p, O[onf][half * 2] * inv, O[onf][half * 2 + 1] * inv);
                *reinterpret_cast<uint32_t*>(ap + token * 512 + off) = p;
            }
        }
        __syncthreads();
    }
}

// ---------------- fp32 SGEMM: both gate tables in ONE launch ----------------
__global__ __launch_bounds__(256)
void gate_tabs_k(const float* __restrict__ vqe, const float* __restrict__ wev,
                 const float* __restrict__ ctx, const float* __restrict__ wct,
                 const float* __restrict__ gb, float* __restrict__ G,
                 float* __restrict__ Cg) {
    const bool isG = (blockIdx.y == 0);
    const float* A = isG ? vqe : ctx;
    const float* W = isG ? wev : wct;
    float* C = isG ? G : Cg;
    const int M = isG ? KC_ : B_;
    const int N = D_, K = D_;

    __shared__ float As[8][129];
    __shared__ float Ws[8][129];
    const int tid = threadIdx.x;
    const int tx = tid & 15, ty = tid >> 4;
    const int m0 = 0, n0 = blockIdx.x * 128;
    const int lm = tid >> 1, lh = tid & 1;

    float acc[8][8];
#pragma unroll
    for (int i = 0; i < 8; i++)
#pragma unroll
        for (int j = 0; j < 8; j++) acc[i][j] = 0.f;

    for (int k0 = 0; k0 < K; k0 += 8) {
        float4 av = make_float4(0.f, 0.f, 0.f, 0.f);
        float4 wv = make_float4(0.f, 0.f, 0.f, 0.f);
        int gm = m0 + lm;
        if (gm < M) av = *reinterpret_cast<const float4*>(A + (long long)gm * K + k0 + lh * 4);
        int gn = n0 + lm;
        if (gn < N) wv = *reinterpret_cast<const float4*>(W + (long long)gn * K + k0 + lh * 4);
        __syncthreads();
        As[lh * 4 + 0][lm] = av.x; As[lh * 4 + 1][lm] = av.y;
        As[lh * 4 + 2][lm] = av.z; As[lh * 4 + 3][lm] = av.w;
        Ws[lh * 4 + 0][lm] = wv.x; Ws[lh * 4 + 1][lm] = wv.y;
        Ws[lh * 4 + 2][lm] = wv.z; Ws[lh * 4 + 3][lm] = wv.w;
        __syncthreads();
#pragma unroll
        for (int kk = 0; kk < 8; kk++) {
            float ra[8], rw[8];
#pragma unroll
            for (int i = 0; i < 8; i++) ra[i] = As[kk][ty + 16 * i];
#pragma unroll
            for (int j = 0; j < 8; j++) rw[j] = Ws[kk][tx + 16 * j];
#pragma unroll
            for (int i = 0; i < 8; i++)
#pragma unroll
                for (int j = 0; j < 8; j++) acc[i][j] += ra[i] * rw[j];
        }
    }
#pragma unroll
    for (int i = 0; i < 8; i++) {
        int gm = m0 + ty + 16 * i;
        if (gm >= M) continue;
#pragma unroll
        for (int j = 0; j < 8; j++) {
            int gn = n0 + tx + 16 * j;
            if (gn >= N) continue;
            float v = acc[i][j];
            if (!isG) v += gb[gn];
            C[(long long)gm * N + gn] = v;
        }
    }
}

// ---------------- merged prep ----------------
__global__ void prep_all_k(const float* __restrict__ abr, const float* __restrict__ abi,
                           const float* __restrict__ gw, const float* __restrict__ vqe,
                           const float* __restrict__ awr, const float* __restrict__ awi,
                           const float* __restrict__ hw, const int* __restrict__ tok,
                           const float* __restrict__ emb,
                           float* __restrict__ bq, float* __restrict__ bz,
                           float* __restrict__ en, float* __restrict__ wev,
                           float* __restrict__ wct,
                           __nv_bfloat16* __restrict__ wq, __nv_bfloat16* __restrict__ wz,
                           __half* __restrict__ vq16, __half* __restrict__ hw16,
                           __nv_bfloat16* __restrict__ x) {
    int blk = blockIdx.x, t = threadIdx.x;
    if (blk < 264) {
        if (blk < 6) {
            int i = blk * 256 + t;
            int seg = i >> 8, j = i & 255, proj = seg >> 1;
            float r = abr[proj * 256 + j], i2 = abi[proj * 256 + j];
            bq[i] = ((seg & 1) == 0) ? (r - i2) : (r + i2);
        } else if (blk == 6) {
            bz[t] = abr[768 + t] - abi[768 + t];
        } else if (blk == 7) {
            if (t < KC_) {
                float a = 0.f;
                for (int d = 0; d < D_; d++) { float e = vqe[t * D_ + d]; a += e * e; }
                en[t] = a;
            }
        } else {
            int i = (blk - 8) * 256 + t;
            int d = i >> 8, j = i & 255;
            wev[i] = gw[d * 3 * D_ + 2 * j];
            wct[i] = gw[d * 3 * D_ + 2 * D_ + j];
        }
    } else if (blk < 1800) {
        long long i = (long long)(blk - 264) * 256 + t;
        int n = (int)(i >> 8), k = (int)(i & 255);
        int seg = n >> 8, j = n & 255, proj = seg >> 1;
        float v = ((seg & 1) == 0) ? awr[((long long)proj * 256 + j) * 256 + k]
                                   : awi[((long long)proj * 256 + j) * 256 + k];
        wq[i] = __float2bfloat16(v);
    } else if (blk < 2312) {
        long long i = (long long)(blk - 1800) * 256 + t;
        int n = (int)(i >> 9), k = (int)(i & 511);
        float v = (k < 256) ? awr[(768LL + n) * 256 + k] : -awi[(768LL + n) * 256 + (k - 256)];
        wz[i] = __float2bfloat16(v);
    } else if (blk < 2440) {
        long long i = (long long)(blk - 2312) * 256 + t;
        vq16[i] = __float2half(vqe[i]);
    } else if (blk < 6536) {
        long long i = (long long)(blk - 2440) * 256 + t;
        hw16[i] = __float2half(hw[i]);
    } else {
        long long i = (long long)(blk - 6536) * 256 + t;
        int token = (int)(i >> 8), d = (int)(i & 255);
        x[i] = __float2bfloat16(emb[(long long)tok[token] * D_ + d]);
    }
}

// ---------------- VQ argmin + loss (Z in fp16) ----------------
__global__ void vq_argmin_k(const float* __restrict__ dot, const float* __restrict__ en,
                            const __half* __restrict__ Z16, const float* __restrict__ E,
                            int* __restrict__ idx_out, float* __restrict__ part) {
    int tkn = blockIdx.x;
    int k = threadIdx.x;
    int wid = k >> 5, lane = k & 31;
    __shared__ float wv[4];
    __shared__ int wi[4];
    __shared__ float ws[4];

    float bv = en[k] - 2.f * dot[(long long)tkn * KC_ + k];
    int bi = k;
#pragma unroll
    for (int off = 16; off > 0; off >>= 1) {
        float ov = __shfl_xor_sync(0xffffffffu, bv, off);
        int oi = __shfl_xor_sync(0xffffffffu, bi, off);
        if (ov < bv || (ov == bv && oi < bi)) { bv = ov; bi = oi; }
    }
    if (lane == 0) { wv[wid] = bv; wi[wid] = bi; }
    __syncthreads();
    float fb = wv[0]; int fi = wi[0];
#pragma unroll
    for (int i = 1; i < 4; i++)
        if (wv[i] < fb || (wv[i] == fb && wi[i] < fi)) { fb = wv[i]; fi = wi[i]; }
    if (k == 0) idx_out[tkn] = fi;

    float acc = 0.f;
#pragma unroll
    for (int d = k; d < D_; d += 128) {
        float diff = E[(long long)fi * D_ + d] - __half2float(Z16[(long long)tkn * 256 + d]);
        acc += diff * diff;
    }
#pragma unroll
    for (int off = 16; off > 0; off >>= 1) acc += __shfl_xor_sync(0xffffffffu, acc, off);
    if (lane == 0) ws[wid] = acc;
    __syncthreads();
    if (k == 0) part[tkn] = ws[0] + ws[1] + ws[2] + ws[3];
}

__global__ void vq_reduce_k(const float* __restrict__ part, float* __restrict__ out_loss) {
    __shared__ float s[256];
    float a = 0.f;
    for (int i = threadIdx.x; i < BL_; i += 256) a += part[i];
    s[threadIdx.x] = a;
    __syncthreads();
    for (int st = 128; st > 0; st >>= 1) {
        if (threadIdx.x < st) s[threadIdx.x] += s[threadIdx.x + st];
        __syncthreads();
    }
    if (threadIdx.x == 0) out_loss[0] = 2.f * s[0] / (float)BLD_;
}

// ---------------- stack partial (gate recomputed) ----------------
__global__ void gate_stack_k(const float* __restrict__ G, const float* __restrict__ Cg,
                             const int* __restrict__ idx, float* __restrict__ part2) {
    int b = blockIdx.x, p = blockIdx.y, d = threadIdx.x;
    float cg = Cg[b * D_ + d];
    float s = 0.f;
    int tbase = b * L_ + p * 64;
#pragma unroll 4
    for (int l = 0; l < 64; l++) {
        int tok = tbase + l;
        float x = G[(long long)idx[tok] * D_ + d] + cg;
        s += 1.f / (1.f + __expf(-x));
    }
    part2[((long long)b * 8 + p) * D_ + d] = s;
}

// ln+modrelu over the (b, codebook) TABLE; reduces part2 inline; kcode==0 rows
// also write the stack_top output (identical add order).
__global__ void ln_tab_k(const float* __restrict__ G, const float* __restrict__ Cg,
                         const float* __restrict__ part2,
                         const float* __restrict__ lg, const float* __restrict__ lb,
                         const float* __restrict__ ib, const float* __restrict__ mb,
                         __half* __restrict__ Ytab16, float* __restrict__ out_stk) {
    int row = blockIdx.x;            // b*128 + k
    int b = row >> 7, kcode = row & 127;
    int d = threadIdx.x;
    int wid = d >> 5, lane = d & 31;
    __shared__ float ws1[8], ws2[8];
    float stk = 0.f;
#pragma unroll
    for (int p = 0; p < 8; p++) stk += part2[((long long)b * 8 + p) * D_ + d];
    if (kcode == 0) out_stk[b * D_ + d] = stk;
    float gx = G[(long long)kcode * D_ + d] + Cg[b * D_ + d];
    float x = 1.f / (1.f + __expf(-gx)) + stk;
    float s1 = x, s2 = x * x;
#pragma unroll
    for (int off = 16; off > 0; off >>= 1) {
        s1 += __shfl_xor_sync(0xffffffffu, s1, off);
        s2 += __shfl_xor_sync(0xffffffffu, s2, off);
    }
    if (lane == 0) { ws1[wid] = s1; ws2[wid] = s2; }
    __syncthreads();
    float t1 = 0.f, t2 = 0.f;
#pragma unroll
    for (int i = 0; i < 8; i++) { t1 += ws1[i]; t2 += ws2[i]; }
    float mu = t1 * (1.f / 256.f);
    float var = t2 * (1.f / 256.f) - mu * mu;
    float nr = (x - mu) * rsqrtf(var + 1e-5f) * lg[d] + lb[d];
    float ni = ib[d];
    float mag = sqrtf(nr * nr + ni * ni);
    float sc = fmaxf(mag + mb[d], 0.f) / (mag + 1e-6f);
    Ytab16[(long long)row * D_ + d] = __float2half(nr * sc);
}

// scatter logits table rows to tokens (streaming stores)
__global__ __launch_bounds__(256)
void scatter_k(const float* __restrict__ LT, const int* __restrict__ idx,
               float* __restrict__ out) {
    int tok = blockIdx.x;
    int b = tok >> 9;
    const float4* src = reinterpret_cast<const float4*>(
        LT + ((size_t)(b * KC_ + idx[tok]) << 12));
    float* dst = out + ((size_t)tok << 12);
    int t = threadIdx.x;
#pragma unroll
    for (int i = 0; i < 4; i++) {
        float4 v = src[t + i * 256];
        STG_CS_F4(dst + (t + i * 256) * 4, v);
    }
}

// ---------------- host launch ----------------
extern "C" void kernel_launch(void* const* d_in, const int* in_sizes, int n_in,
                              void* d_out, int out_size) {
    const int*   tokens = (const int*)d_in[0];
    const float* context = (const float*)d_in[1];
    const float* emb = (const float*)d_in[2];
    const float* awr = (const float*)d_in[3];
    const float* awi = (const float*)d_in[4];
    const float* abr = (const float*)d_in[5];
    const float* abi = (const float*)d_in[6];
    const float* vqe = (const float*)d_in[7];
    const float* gw  = (const float*)d_in[8];
    const float* gb  = (const float*)d_in[9];
    const float* lrg = (const float*)d_in[10];
    const float* lrb = (const float*)d_in[11];
    const float* lib = (const float*)d_in[13];
    const float* mrb = (const float*)d_in[14];
    const float* hw  = (const float*)d_in[15];
    const float* hb  = (const float*)d_in[16];
    float* out = (float*)d_out;

    float* S; cudaGetSymbolAddress((void**)&S, d_scratch);
    __nv_bfloat16* BF; cudaGetSymbolAddress((void**)&BF, d_bf);
    __half* HF; cudaGetSymbolAddress((void**)&HF, d_hf);
    int* idxb; cudaGetSymbolAddress((void**)&idxb, d_idxbuf);

    cudaFuncSetAttribute(gemmS<true>,  cudaFuncAttributeMaxDynamicSharedMemorySize, GS_SMEM);
    cudaFuncSetAttribute(gemmS<false>, cudaFuncAttributeMaxDynamicSharedMemorySize, GS_SMEM);
    cudaFuncSetAttribute(gemm1<0>, cudaFuncAttributeMaxDynamicSharedMemorySize, G1_SMEM);
    cudaFuncSetAttribute(gemm1<1>, cudaFuncAttributeMaxDynamicSharedMemorySize, G1_SMEM);
    cudaFuncSetAttribute(attn_mma, cudaFuncAttributeMaxDynamicSharedMemorySize, ATT_SMEM);

    float* DOT   = S + OFF_DOT;
    float* LT    = S + OFF_LT;
    float* G     = S + OFF_G;
    float* Cg    = S + OFF_CG;
    float* wev   = S + OFF_WEV;
    float* wct   = S + OFF_WCT;
    float* en    = S + OFF_EN;
    float* part  = S + OFF_PART;
    float* bqkv  = S + OFF_BQKV;
    float* bzr   = S + OFF_BZR;
    float* part2 = S + OFF_PART2;

    __nv_bfloat16* XBF  = BF + BF_X;
    __nv_bfloat16* WQBF = BF + BF_WQ;
    __nv_bfloat16* QKVB = BF + BF_QKV;
    __nv_bfloat16* APB  = BF + BF_AP;
    __nv_bfloat16* WZBF = BF + BF_WZ;

    __half* HW16 = HF + HF_HW;
    __half* Y16  = HF + HF_Y;
    __half* Z16  = HF + HF_Z;
    __half* VQ16 = HF + HF_VQ;

    prep_all_k<<<22920, 256>>>(abr, abi, gw, vqe, awr, awi, hw, tokens, emb,
                               bqkv, bzr, en, wev, wct,
                               WQBF, WZBF, VQ16, HW16, XBF);

    // QKV GEMM (128x128, 2 CTA/SM) -> bf16 packed QKV
    gemm1<0><<<dim3(1536 / 128, BL_ / 128), 256, G1_SMEM>>>(
        XBF, WQBF, bqkv, QKVB, nullptr, 1536, 256);

    // flash attention (K/V resident per (b,h))
    attn_mma<<<B_ * H_, 256, ATT_SMEM>>>(QKVB, APB);

    // out clinear -> Z16 fp16 only
    gemm1<1><<<dim3(256 / 128, BL_ / 128), 256, G1_SMEM>>>(
        APB, WZBF, bzr, nullptr, Z16, 256, 512);

    // VQ dot + argmin + loss
    gemmS<false><<<dim3(1, BL_ / 256), 512, GS_SMEM>>>(
        Z16, VQ16, nullptr, DOT, KC_, 256);
    vq_argmin_k<<<BL_, 128>>>(DOT, en, Z16, vqe, idxb, part);
    vq_reduce_k<<<1, 256>>>(part, out + BLV_);

    // gate tables (single launch)
    gate_tabs_k<<<dim3(2, 2), 256>>>(vqe, wev, context, wct, gb, G, Cg);

    // stack partials; ln_tab reduces part2 + writes stack_top output
    gate_stack_k<<<dim3(B_, 8), 256>>>(G, Cg, idxb, part2);
    ln_tab_k<<<NTAB, D_>>>(G, Cg, part2, lrg, lrb, lib, mrb, Y16, out + BLV_ + 1);

    // head GEMM on the table: LT (4096 x 4096) = Ytab @ hw^T + hb
    gemmS<true><<<dim3(V_ / 128, NTAB / 256), 512, GS_SMEM>>>(
        Y16, HW16, hb, LT, V_, 256);

    // scatter table rows to all tokens
    scatter_k<<<BL_, 256>>>(LT, idxb, out);
}

// round 17
// speedup vs baseline: 2.0388x; 1.0058x over previous
#include <cuda_runtime.h>
#include <cuda_bf16.h>
#include <cuda_fp16.h>
#include <cstdint>
#include <math.h>

// ---------------- problem dims ----------------
constexpr int B_ = 32, L_ = 512, D_ = 256, H_ = 8, V_ = 4096, KC_ = 128;
constexpr int BL_ = B_ * L_;                 // 16384
constexpr long long BLD_ = (long long)BL_ * D_;   // 4194304
constexpr long long BLV_ = (long long)BL_ * V_;   // 67108864
constexpr int NTAB = B_ * KC_;               // 4096 distinct (b, idx) rows

// ---------------- fp32 scratch ----------------
constexpr long long OFF_DOT   = 0;                               // BL*128
constexpr long long OFF_LT    = OFF_DOT + (long long)BL_ * KC_;  // NTAB*V
constexpr long long OFF_G     = OFF_LT + (long long)NTAB * V_;
constexpr long long OFF_CG    = OFF_G + (long long)KC_ * D_;
constexpr long long OFF_WEV   = OFF_CG + (long long)B_ * D_;
constexpr long long OFF_WCT   = OFF_WEV + (long long)D_ * D_;
constexpr long long OFF_EN    = OFF_WCT + (long long)D_ * D_;
constexpr long long OFF_PART  = OFF_EN + KC_;
constexpr long long OFF_BQKV  = OFF_PART + BL_;
constexpr long long OFF_BZR   = OFF_BQKV + 1536;
constexpr long long OFF_PART2 = OFF_BZR + 256;                   // 32*8*256
constexpr long long SCRATCH_N = OFF_PART2 + 32LL * 8 * 256 + 64;

__device__ float d_scratch[SCRATCH_N];
__device__ int   d_idxbuf[BL_];

// ---------------- bf16 scratch ----------------
constexpr long long BF_X    = 0;                                // BLD
constexpr long long BF_WQ   = BF_X + BLD_;                      // 1536*256
constexpr long long BF_QKV  = BF_WQ + 1536LL * 256;             // BL*1536
constexpr long long BF_AP   = BF_QKV + (long long)BL_ * 1536;   // BL*512
constexpr long long BF_WZ   = BF_AP + (long long)BL_ * 512;     // 256*512
constexpr long long BF_N    = BF_WZ + 256LL * 512 + 64;

__device__ __nv_bfloat16 d_bf[BF_N];

// ---------------- fp16 scratch ----------------
constexpr long long HF_HW  = 0;                                 // V*D
constexpr long long HF_Y   = HF_HW + (long long)V_ * D_;        // NTAB*D
constexpr long long HF_Z   = HF_Y + (long long)NTAB * D_;       // BLD
constexpr long long HF_VQ  = HF_Z + BLD_;                       // KC*D
constexpr long long HF_N   = HF_VQ + (long long)KC_ * D_ + 64;

__device__ __half d_hf[HF_N];

// ==================== PTX helpers ====================
__device__ __forceinline__ uint32_t smem_u32(const void* p) {
    uint32_t a;
    asm("{ .reg .u64 t; cvta.to.shared.u64 t, %1; cvt.u32.u64 %0, t; }" : "=r"(a) : "l"(p));
    return a;
}
#define CP_ASYNC16(dst, src) \
    asm volatile("cp.async.cg.shared.global [%0], [%1], 16;" :: "r"(dst), "l"(src))
#define CP_COMMIT() asm volatile("cp.async.commit_group;" ::: "memory")
#define CP_WAIT(n)  asm volatile("cp.async.wait_group %0;" :: "n"(n) : "memory")
#define LDSM_X4(r, addr) \
    asm volatile("ldmatrix.sync.aligned.m8n8.x4.shared.b16 {%0,%1,%2,%3}, [%4];" \
                 : "=r"((r)[0]), "=r"((r)[1]), "=r"((r)[2]), "=r"((r)[3]) : "r"(addr))
#define LDSM_X4_T(r, addr) \
    asm volatile("ldmatrix.sync.aligned.m8n8.x4.trans.shared.b16 {%0,%1,%2,%3}, [%4];" \
                 : "=r"((r)[0]), "=r"((r)[1]), "=r"((r)[2]), "=r"((r)[3]) : "r"(addr))
#define MMA_BF16(d, a, b) \
    asm volatile("mma.sync.aligned.m16n8k16.row.col.f32.bf16.bf16.f32 " \
                 "{%0,%1,%2,%3}, {%4,%5,%6,%7}, {%8,%9}, {%0,%1,%2,%3};" \
                 : "+f"((d)[0]), "+f"((d)[1]), "+f"((d)[2]), "+f"((d)[3]) \
                 : "r"((a)[0]), "r"((a)[1]), "r"((a)[2]), "r"((a)[3]), \
                   "r"((b)[0]), "r"((b)[1]))
#define MMA_FP16(d, a, b) \
    asm volatile("mma.sync.aligned.m16n8k16.row.col.f32.f16.f16.f32 " \
                 "{%0,%1,%2,%3}, {%4,%5,%6,%7}, {%8,%9}, {%0,%1,%2,%3};" \
                 : "+f"((d)[0]), "+f"((d)[1]), "+f"((d)[2]), "+f"((d)[3]) \
                 : "r"((a)[0]), "r"((a)[1]), "r"((a)[2]), "r"((a)[3]), \
                   "r"((b)[0]), "r"((b)[1]))
// d.lo = lo, d.hi = hi
#define PACK_BF16X2(d, lo, hi) \
    asm("cvt.rn.bf16x2.f32 %0, %1, %2;" : "=r"(d) : "f"(hi), "f"(lo))
#define PACK_F16X2(d, lo, hi) \
    asm("cvt.rn.f16x2.f32 %0, %1, %2;" : "=r"(d) : "f"(hi), "f"(lo))
#define STG_CS_F4(ptr, v) \
    asm volatile("st.global.cs.v4.f32 [%0], {%1, %2, %3, %4};" \
                 :: "l"(ptr), "f"((v).x), "f"((v).y), "f"((v).z), "f"((v).w))

constexpr int LDT = 40;                         // padded row stride (16-bit elems)

// ==================== single-fp16 HMMA GEMM, 256x128 CTA tile, 512 threads ====================
constexpr int TS_A = 256 * LDT * 2;             // 20480
constexpr int TS_B = 128 * LDT * 2;             // 10240
constexpr int STAGES = TS_A + TS_B;             // 30720
constexpr int GS_SMEM = 3 * STAGES;             // 92160

template<bool BIAS>
__global__ __launch_bounds__(512, 1)
void gemmS(const __half* __restrict__ A, const __half* __restrict__ B,
           const float* __restrict__ bias, float* __restrict__ C,
           int N, int K) {
    extern __shared__ char smem[];
    const uint32_t sb = smem_u32(smem);
    const int tid = threadIdx.x, wid = tid >> 5, lane = tid & 31;
    const int m0 = blockIdx.y * 256, n0 = blockIdx.x * 128;
    const int mW = (wid & 7) * 32, nW = (wid >> 3) * 64;

    float acc[2][8][4];
#pragma unroll
    for (int i = 0; i < 2; i++)
#pragma unroll
        for (int j = 0; j < 8; j++)
#pragma unroll
            for (int c = 0; c < 4; c++) acc[i][j][c] = 0.f;

    auto load_stage = [&](int buf, int k0) {
        const uint32_t st = sb + buf * STAGES;
#pragma unroll
        for (int it = 0; it < 2; it++) {
            int c = it * 512 + tid;
            int row = c >> 2, cc = c & 3;
            CP_ASYNC16(st + (uint32_t)(row * LDT + cc * 8) * 2,
                       A + (size_t)(m0 + row) * K + k0 + cc * 8);
        }
        {
            int c = tid;
            int row = c >> 2, cc = c & 3;
            CP_ASYNC16(st + TS_A + (uint32_t)(row * LDT + cc * 8) * 2,
                       B + (size_t)(n0 + row) * K + k0 + cc * 8);
        }
        CP_COMMIT();
    };

    auto a_addr = [&](uint32_t base, int mBase, int k0) -> uint32_t {
        int t = lane >> 3;
        int r = mBase + ((t & 1) << 3) + (lane & 7);
        int c = k0 + ((t >> 1) << 3);
        return base + (uint32_t)(r * LDT + c) * 2;
    };
    auto b_addr = [&](uint32_t base, int nBase, int k0) -> uint32_t {
        int t = lane >> 3;
        int n = nBase + ((t >> 1) << 3) + (lane & 7);
        int c = k0 + ((t & 1) << 3);
        return base + (uint32_t)(n * LDT + c) * 2;
    };

    const int S = K >> 5;
    load_stage(0, 0);
    load_stage(1, 32);

    for (int s = 0; s < S; s++) {
        const int buf = s % 3;
        if (s + 1 < S) { CP_WAIT(1); } else { CP_WAIT(0); }
        __syncthreads();
        if (s + 2 < S) load_stage((s + 2) % 3, (s + 2) << 5);

        const uint32_t aS = sb + buf * STAGES;
        const uint32_t bS = aS + TS_A;

        uint32_t af[2][2][4];
#pragma unroll
        for (int kk = 0; kk < 2; kk++)
#pragma unroll
            for (int mf = 0; mf < 2; mf++)
                LDSM_X4(af[kk][mf], a_addr(aS, mW + mf * 16, kk * 16));

#pragma unroll
        for (int kk = 0; kk < 2; kk++) {
            const int k0 = kk * 16;
#pragma unroll
            for (int nf2 = 0; nf2 < 4; nf2++) {
                uint32_t r[4];
                LDSM_X4(r, b_addr(bS, nW + nf2 * 16, k0));
                uint32_t b01[2] = {r[0], r[1]}, b23[2] = {r[2], r[3]};
#pragma unroll
                for (int mf = 0; mf < 2; mf++) {
                    MMA_FP16(acc[mf][nf2 * 2], af[kk][mf], b01);
                    MMA_FP16(acc[mf][nf2 * 2 + 1], af[kk][mf], b23);
                }
            }
        }
    }
    __syncthreads();

    const int lr = lane >> 2, lc = (lane & 3) * 2;
#pragma unroll
    for (int mf = 0; mf < 2; mf++) {
        int row0 = m0 + mW + mf * 16 + lr;
#pragma unroll
        for (int nf = 0; nf < 8; nf++) {
            int col = n0 + nW + nf * 8 + lc;
            float b0 = 0.f, b1 = 0.f;
            if (BIAS) { b0 = bias[col]; b1 = bias[col + 1]; }
            *reinterpret_cast<float2*>(C + (size_t)row0 * N + col) =
                make_float2(acc[mf][nf][0] + b0, acc[mf][nf][1] + b1);
            *reinterpret_cast<float2*>(C + (size_t)(row0 + 8) * N + col) =
                make_float2(acc[mf][nf][2] + b0, acc[mf][nf][3] + b1);
        }
    }
}

// ==================== 16-bit HMMA GEMM (128x128, 2 CTA/SM) ====================
// F16IN false: bf16 inputs (MMA_BF16); true: fp16 inputs (MMA_FP16).
// OUTM 0: bf16 out (+bias) -> Ch.  OUTM 1: fp16 out (+bias) -> Ch16.
// OUTM 2: fp32 out (no bias) -> Cf.
constexpr int TILE_B1 = 128 * LDT * 2;            // 10240
constexpr int STAGE_B1 = 2 * TILE_B1;             // 20480
constexpr int G1_SMEM = 3 * STAGE_B1;             // 61440

template<int OUTM, bool F16IN>
__global__ __launch_bounds__(256, 2)
void gemm1(const __nv_bfloat16* __restrict__ A, const __nv_bfloat16* __restrict__ B,
           const float* __restrict__ bias, __nv_bfloat16* __restrict__ Ch,
           __half* __restrict__ Ch16, float* __restrict__ Cf, int N, int K) {
    extern __shared__ char smem[];
    const uint32_t sb = smem_u32(smem);
    const int tid = threadIdx.x, wid = tid >> 5, lane = tid & 31;
    const int m0 = blockIdx.y * 128, n0 = blockIdx.x * 128;
    const int warpM = wid & 1, warpN = wid >> 1;
    const int mW = warpM * 64, nW = warpN * 32;

    float acc[4][4][4];
#pragma unroll
    for (int i = 0; i < 4; i++)
#pragma unroll
        for (int j = 0; j < 4; j++)
#pragma unroll
            for (int c = 0; c < 4; c++) acc[i][j][c] = 0.f;

    auto load_stage = [&](int buf, int k0) {
#pragma unroll
        for (int mtx = 0; mtx < 2; mtx++) {
            const __nv_bfloat16* src = (mtx == 0) ? A : B;
            const int rbase = (mtx == 0) ? m0 : n0;
            uint32_t dst = sb + buf * STAGE_B1 + mtx * TILE_B1;
#pragma unroll
            for (int it = 0; it < 2; it++) {
                int c = it * 256 + tid;
                int row = c >> 2, cc = c & 3;
                CP_ASYNC16(dst + (uint32_t)(row * LDT + cc * 8) * 2,
                           src + (size_t)(rbase + row) * K + k0 + cc * 8);
            }
        }
        CP_COMMIT();
    };

    auto a_addr = [&](uint32_t base, int mBase, int k0) -> uint32_t {
        int t = lane >> 3;
        int r = mBase + ((t & 1) << 3) + (lane & 7);
        int c = k0 + ((t >> 1) << 3);
        return base + (uint32_t)(r * LDT + c) * 2;
    };
    auto b_addr = [&](uint32_t base, int nBase, int k0) -> uint32_t {
        int t = lane >> 3;
        int n = nBase + ((t >> 1) << 3) + (lane & 7);
        int c = k0 + ((t & 1) << 3);
        return base + (uint32_t)(n * LDT + c) * 2;
    };

    const int S = K >> 5;
    load_stage(0, 0);
    load_stage(1, 32);

    for (int s = 0; s < S; s++) {
        const int buf = s % 3;
        if (s + 1 < S) { CP_WAIT(1); } else { CP_WAIT(0); }
        __syncthreads();
        if (s + 2 < S) load_stage((s + 2) % 3, (s + 2) << 5);

        const uint32_t aB = sb + buf * STAGE_B1;
        const uint32_t bB = aB + TILE_B1;

        uint32_t af[2][4][4];
#pragma unroll
        for (int kk = 0; kk < 2; kk++)
#pragma unroll
            for (int mf = 0; mf < 4; mf++)
                LDSM_X4(af[kk][mf], a_addr(aB, mW + mf * 16, kk * 16));

#pragma unroll
        for (int kk = 0; kk < 2; kk++) {
            const int k0 = kk * 16;
#pragma unroll
            for (int nf2 = 0; nf2 < 2; nf2++) {
                uint32_t r[4];
                LDSM_X4(r, b_addr(bB, nW + nf2 * 16, k0));
                uint32_t b01[2] = {r[0], r[1]}, b23[2] = {r[2], r[3]};
#pragma unroll
                for (int mf = 0; mf < 4; mf++) {
                    if (F16IN) {
                        MMA_FP16(acc[mf][nf2 * 2], af[kk][mf], b01);
                        MMA_FP16(acc[mf][nf2 * 2 + 1], af[kk][mf], b23);
                    } else {
                        MMA_BF16(acc[mf][nf2 * 2], af[kk][mf], b01);
                        MMA_BF16(acc[mf][nf2 * 2 + 1], af[kk][mf], b23);
                    }
                }
            }
        }
    }
    __syncthreads();

    const int lr = lane >> 2, lc = (lane & 3) * 2;
#pragma unroll
    for (int mf = 0; mf < 4; mf++) {
        int row0 = m0 + mW + mf * 16 + lr;
#pragma unroll
        for (int nf = 0; nf < 4; nf++) {
            int col = n0 + nW + nf * 8 + lc;
            float b0 = (OUTM != 2 && bias) ? bias[col] : 0.f;
            float b1 = (OUTM != 2 && bias) ? bias[col + 1] : 0.f;
#pragma unroll
            for (int half = 0; half < 2; half++) {
                size_t row = (size_t)(row0 + half * 8);
                float v0 = acc[mf][nf][half * 2] + b0;
                float v1 = acc[mf][nf][half * 2 + 1] + b1;
                if (OUTM == 0) {
                    uint32_t p; PACK_BF16X2(p, v0, v1);
                    *reinterpret_cast<uint32_t*>(Ch + row * N + col) = p;
                } else if (OUTM == 1) {
                    uint32_t ph; PACK_F16X2(ph, v0, v1);
                    *reinterpret_cast<uint32_t*>(Ch16 + row * N + col) = ph;
                } else {
                    *reinterpret_cast<float2*>(Cf + row * N + col) = make_float2(v0, v1);
                }
            }
        }
    }
}

// ==================== bf16 HMMA flash attention, K/V resident ====================
constexpr int ALD = 72;
constexpr int AK_OFF = 0;
constexpr int AV_OFF = 512 * ALD * 2;
constexpr int AQ_OFF = AV_OFF + 512 * ALD * 2;
constexpr int ATT_SMEM = AQ_OFF + 128 * ALD * 2;   // 165888

__global__ __launch_bounds__(256, 1)
void attn_mma(const __nv_bfloat16* __restrict__ qkv, __nv_bfloat16* __restrict__ ap) {
    extern __shared__ char smem[];
    const uint32_t sKb = smem_u32(smem) + AK_OFF;
    const uint32_t sVb = smem_u32(smem) + AV_OFF;
    const uint32_t sQb = smem_u32(smem) + AQ_OFF;

    const int bid = blockIdx.x;
    const int h = bid & 7, b = bid >> 3;
    const int tid = threadIdx.x, wid = tid >> 5, lane = tid & 31;
    const size_t tok0 = (size_t)b * L_;
    const int hoff = h * 32;

#pragma unroll
    for (int i = 0; i < 16; i++) {
        int c = i * 256 + tid;
        int row = c >> 3, u = c & 7, seg = u >> 2, j = u & 3;
        CP_ASYNC16(sKb + (uint32_t)(row * ALD + seg * 32 + j * 8) * 2,
                   qkv + (tok0 + row) * 1536 + hoff + 512 + seg * 256 + j * 8);
    }
#pragma unroll
    for (int i = 0; i < 16; i++) {
        int c = i * 256 + tid;
        int row = c >> 3, u = c & 7, seg = u >> 2, j = u & 3;
        CP_ASYNC16(sVb + (uint32_t)(row * ALD + seg * 32 + j * 8) * 2,
                   qkv + (tok0 + row) * 1536 + hoff + 1024 + seg * 256 + j * 8);
    }
    CP_COMMIT();

    auto a_addr = [&](uint32_t base, int mBase, int k0) -> uint32_t {
        int t = lane >> 3;
        int r = mBase + ((t & 1) << 3) + (lane & 7);
        int c = k0 + ((t >> 1) << 3);
        return base + (uint32_t)(r * ALD + c) * 2;
    };
    auto b_addr = [&](uint32_t base, int nBase, int k0) -> uint32_t {
        int t = lane >> 3;
        int n = nBase + ((t >> 1) << 3) + (lane & 7);
        int c = k0 + ((t & 1) << 3);
        return base + (uint32_t)(n * ALD + c) * 2;
    };

    const float scale = 0.17677669529663687f;

    for (int qt = 0; qt < 4; qt++) {
#pragma unroll
        for (int i = 0; i < 4; i++) {
            int c = i * 256 + tid;
            int row = c >> 3, u = c & 7, seg = u >> 2, j = u & 3;
            uint4 v = *reinterpret_cast<const uint4*>(
                qkv + (tok0 + qt * 128 + row) * 1536 + hoff + seg * 256 + j * 8);
            *reinterpret_cast<uint4*>(reinterpret_cast<__nv_bfloat16*>(smem) +
                (AQ_OFF / 2) + row * ALD + seg * 32 + j * 8) = v;
        }
        if (qt == 0) CP_WAIT(0);
        __syncthreads();

        uint32_t aQ[4][4];
#pragma unroll
        for (int kf = 0; kf < 4; kf++) LDSM_X4(aQ[kf], a_addr(sQb, wid * 16, kf * 16));

        float O[8][4];
#pragma unroll
        for (int i = 0; i < 8; i++)
#pragma unroll
            for (int c = 0; c < 4; c++) O[i][c] = 0.f;
        float m0r = -1e30f, m1r = -1e30f, l0 = 0.f, l1 = 0.f;

#pragma unroll
        for (int kc = 0; kc < 4; kc++) {
            const uint32_t kChunk = sKb + (uint32_t)(kc * 128 * ALD) * 2;
            const uint32_t vChunk = sVb + (uint32_t)(kc * 128 * ALD) * 2;

            float S[16][4];
#pragma unroll
            for (int nf = 0; nf < 16; nf++)
#pragma unroll
                for (int c = 0; c < 4; c++) S[nf][c] = 0.f;
#pragma unroll
            for (int kf = 0; kf < 4; kf++) {
#pragma unroll
                for (int nf2 = 0; nf2 < 8; nf2++) {
                    uint32_t r[4];
                    LDSM_X4(r, b_addr(kChunk, nf2 * 16, kf * 16));
                    uint32_t b01[2] = {r[0], r[1]}, b23[2] = {r[2], r[3]};
                    MMA_BF16(S[nf2 * 2], aQ[kf], b01);
                    MMA_BF16(S[nf2 * 2 + 1], aQ[kf], b23);
                }
            }
            float mx0 = -1e30f, mx1 = -1e30f;
#pragma unroll
            for (int nf = 0; nf < 16; nf++) {
#pragma unroll
                for (int c = 0; c < 4; c++) S[nf][c] *= scale;
                mx0 = fmaxf(mx0, fmaxf(S[nf][0], S[nf][1]));
                mx1 = fmaxf(mx1, fmaxf(S[nf][2], S[nf][3]));
            }
            mx0 = fmaxf(mx0, __shfl_xor_sync(0xffffffffu, mx0, 1));
            mx0 = fmaxf(mx0, __shfl_xor_sync(0xffffffffu, mx0, 2));
            mx1 = fmaxf(mx1, __shfl_xor_sync(0xffffffffu, mx1, 1));
            mx1 = fmaxf(mx1, __shfl_xor_sync(0xffffffffu, mx1, 2));
            float mn0 = fmaxf(m0r, mx0), mn1 = fmaxf(m1r, mx1);
            float al0 = __expf(m0r - mn0), al1 = __expf(m1r - mn1);
            m0r = mn0; m1r = mn1;
            float rs0 = 0.f, rs1 = 0.f;
#pragma unroll
            for (int nf = 0; nf < 16; nf++) {
                S[nf][0] = __expf(S[nf][0] - mn0);
                S[nf][1] = __expf(S[nf][1] - mn0);
                S[nf][2] = __expf(S[nf][2] - mn1);
                S[nf][3] = __expf(S[nf][3] - mn1);
                rs0 += S[nf][0] + S[nf][1];
                rs1 += S[nf][2] + S[nf][3];
            }
            rs0 += __shfl_xor_sync(0xffffffffu, rs0, 1);
            rs0 += __shfl_xor_sync(0xffffffffu, rs0, 2);
            rs1 += __shfl_xor_sync(0xffffffffu, rs1, 1);
            rs1 += __shfl_xor_sync(0xffffffffu, rs1, 2);
            l0 = l0 * al0 + rs0;
            l1 = l1 * al1 + rs1;
#pragma unroll
            for (int i = 0; i < 8; i++) {
                O[i][0] *= al0; O[i][1] *= al0; O[i][2] *= al1; O[i][3] *= al1;
            }
#pragma unroll
            for (int t8 = 0; t8 < 8; t8++) {
                uint32_t pa[4];
                PACK_BF16X2(pa[0], S[2 * t8][0], S[2 * t8][1]);
                PACK_BF16X2(pa[1], S[2 * t8][2], S[2 * t8][3]);
                PACK_BF16X2(pa[2], S[2 * t8 + 1][0], S[2 * t8 + 1][1]);
                PACK_BF16X2(pa[3], S[2 * t8 + 1][2], S[2 * t8 + 1][3]);
#pragma unroll
                for (int vn2 = 0; vn2 < 4; vn2++) {
                    uint32_t r[4];
                    LDSM_X4_T(r, a_addr(vChunk, t8 * 16, vn2 * 16));
                    uint32_t b01[2] = {r[0], r[1]}, b23[2] = {r[2], r[3]};
                    MMA_BF16(O[vn2 * 2], pa, b01);
                    MMA_BF16(O[vn2 * 2 + 1], pa, b23);
                }
            }
        }

        float i0 = 1.f / l0, i1 = 1.f / l1;
        const int r = lane >> 2, cq = (lane & 3) * 2;
#pragma unroll
        for (int onf = 0; onf < 8; onf++) {
            int vc = onf * 8 + cq;
            int off = (vc < 32) ? (hoff + vc) : (256 + hoff + vc - 32);
#pragma unroll
            for (int half = 0; half < 2; half++) {
                size_t token = tok0 + qt * 128 + wid * 16 + r + half * 8;
                float inv = half ? i1 : i0;
                uint32_t p;
                PACK_BF16X2(p, O[onf][half * 2] * inv, O[onf][half * 2 + 1] * inv);
                *reinterpret_cast<uint32_t*>(ap + token * 512 + off) = p;
            }
        }
        __syncthreads();
    }
}

// ---------------- fp32 SGEMM: both gate tables in ONE launch ----------------
__global__ __launch_bounds__(256)
void gate_tabs_k(const float* __restrict__ vqe, const float* __restrict__ wev,
                 const float* __restrict__ ctx, const float* __restrict__ wct,
                 const float* __restrict__ gb, float* __restrict__ G,
                 float* __restrict__ Cg) {
    const bool isG = (blockIdx.y == 0);
    const float* A = isG ? vqe : ctx;
    const float* W = isG ? wev : wct;
    float* C = isG ? G : Cg;
    const int M = isG ? KC_ : B_;
    const int N = D_, K = D_;

    __shared__ float As[8][129];
    __shared__ float Ws[8][129];
    const int tid = threadIdx.x;
    const int tx = tid & 15, ty = tid >> 4;
    const int m0 = 0, n0 = blockIdx.x * 128;
    const int lm = tid >> 1, lh = tid & 1;

    float acc[8][8];
#pragma unroll
    for (int i = 0; i < 8; i++)
#pragma unroll
        for (int j = 0; j < 8; j++) acc[i][j] = 0.f;

    for (int k0 = 0; k0 < K; k0 += 8) {
        float4 av = make_float4(0.f, 0.f, 0.f, 0.f);
        float4 wv = make_float4(0.f, 0.f, 0.f, 0.f);
        int gm = m0 + lm;
        if (gm < M) av = *reinterpret_cast<const float4*>(A + (long long)gm * K + k0 + lh * 4);
        int gn = n0 + lm;
        if (gn < N) wv = *reinterpret_cast<const float4*>(W + (long long)gn * K + k0 + lh * 4);
        __syncthreads();
        As[lh * 4 + 0][lm] = av.x; As[lh * 4 + 1][lm] = av.y;
        As[lh * 4 + 2][lm] = av.z; As[lh * 4 + 3][lm] = av.w;
        Ws[lh * 4 + 0][lm] = wv.x; Ws[lh * 4 + 1][lm] = wv.y;
        Ws[lh * 4 + 2][lm] = wv.z; Ws[lh * 4 + 3][lm] = wv.w;
        __syncthreads();
#pragma unroll
        for (int kk = 0; kk < 8; kk++) {
            float ra[8], rw[8];
#pragma unroll
            for (int i = 0; i < 8; i++) ra[i] = As[kk][ty + 16 * i];
#pragma unroll
            for (int j = 0; j < 8; j++) rw[j] = Ws[kk][tx + 16 * j];
#pragma unroll
            for (int i = 0; i < 8; i++)
#pragma unroll
                for (int j = 0; j < 8; j++) acc[i][j] += ra[i] * rw[j];
        }
    }
#pragma unroll
    for (int i = 0; i < 8; i++) {
        int gm = m0 + ty + 16 * i;
        if (gm >= M) continue;
#pragma unroll
        for (int j = 0; j < 8; j++) {
            int gn = n0 + tx + 16 * j;
            if (gn >= N) continue;
            float v = acc[i][j];
            if (!isG) v += gb[gn];
            C[(long long)gm * N + gn] = v;
        }
    }
}

// ---------------- merged prep ----------------
__global__ void prep_all_k(const float* __restrict__ abr, const float* __restrict__ abi,
                           const float* __restrict__ gw, const float* __restrict__ vqe,
                           const float* __restrict__ awr, const float* __restrict__ awi,
                           const float* __restrict__ hw, const int* __restrict__ tok,
                           const float* __restrict__ emb,
                           float* __restrict__ bq, float* __restrict__ bz,
                           float* __restrict__ en, float* __restrict__ wev,
                           float* __restrict__ wct,
                           __nv_bfloat16* __restrict__ wq, __nv_bfloat16* __restrict__ wz,
                           __half* __restrict__ vq16, __half* __restrict__ hw16,
                           __nv_bfloat16* __restrict__ x) {
    int blk = blockIdx.x, t = threadIdx.x;
    if (blk < 264) {
        if (blk < 6) {
            int i = blk * 256 + t;
            int seg = i >> 8, j = i & 255, proj = seg >> 1;
            float r = abr[proj * 256 + j], i2 = abi[proj * 256 + j];
            bq[i] = ((seg & 1) == 0) ? (r - i2) : (r + i2);
        } else if (blk == 6) {
            bz[t] = abr[768 + t] - abi[768 + t];
        } else if (blk == 7) {
            if (t < KC_) {
                float a = 0.f;
                for (int d = 0; d < D_; d++) { float e = vqe[t * D_ + d]; a += e * e; }
                en[t] = a;
            }
        } else {
            int i = (blk - 8) * 256 + t;
            int d = i >> 8, j = i & 255;
            wev[i] = gw[d * 3 * D_ + 2 * j];
            wct[i] = gw[d * 3 * D_ + 2 * D_ + j];
        }
    } else if (blk < 1800) {
        long long i = (long long)(blk - 264) * 256 + t;
        int n = (int)(i >> 8), k = (int)(i & 255);
        int seg = n >> 8, j = n & 255, proj = seg >> 1;
        float v = ((seg & 1) == 0) ? awr[((long long)proj * 256 + j) * 256 + k]
                                   : awi[((long long)proj * 256 + j) * 256 + k];
        wq[i] = __float2bfloat16(v);
    } else if (blk < 2312) {
        long long i = (long long)(blk - 1800) * 256 + t;
        int n = (int)(i >> 9), k = (int)(i & 511);
        float v = (k < 256) ? awr[(768LL + n) * 256 + k] : -awi[(768LL + n) * 256 + (k - 256)];
        wz[i] = __float2bfloat16(v);
    } else if (blk < 2440) {
        long long i = (long long)(blk - 2312) * 256 + t;
        vq16[i] = __float2half(vqe[i]);
    } else if (blk < 6536) {
        long long i = (long long)(blk - 2440) * 256 + t;
        hw16[i] = __float2half(hw[i]);
    } else {
        long long i = (long long)(blk - 6536) * 256 + t;
        int token = (int)(i >> 8), d = (int)(i & 255);
        x[i] = __float2bfloat16(emb[(long long)tok[token] * D_ + d]);
    }
}

// ---------------- VQ argmin + loss (Z in fp16) ----------------
__global__ void vq_argmin_k(const float* __restrict__ dot, const float* __restrict__ en,
                            const __half* __restrict__ Z16, const float* __restrict__ E,
                            int* __restrict__ idx_out, float* __restrict__ part) {
    int tkn = blockIdx.x;
    int k = threadIdx.x;
    int wid = k >> 5, lane = k & 31;
    __shared__ float wv[4];
    __shared__ int wi[4];
    __shared__ float ws[4];

    float bv = en[k] - 2.f * dot[(long long)tkn * KC_ + k];
    int bi = k;
#pragma unroll
    for (int off = 16; off > 0; off >>= 1) {
        float ov = __shfl_xor_sync(0xffffffffu, bv, off);
        int oi = __shfl_xor_sync(0xffffffffu, bi, off);
        if (ov < bv || (ov == bv && oi < bi)) { bv = ov; bi = oi; }
    }
    if (lane == 0) { wv[wid] = bv; wi[wid] = bi; }
    __syncthreads();
    float fb = wv[0]; int fi = wi[0];
#pragma unroll
    for (int i = 1; i < 4; i++)
        if (wv[i] < fb || (wv[i] == fb && wi[i] < fi)) { fb = wv[i]; fi = wi[i]; }
    if (k == 0) idx_out[tkn] = fi;

    float acc = 0.f;
#pragma unroll
    for (int d = k; d < D_; d += 128) {
        float diff = E[(long long)fi * D_ + d] - __half2float(Z16[(long long)tkn * 256 + d]);
        acc += diff * diff;
    }
#pragma unroll
    for (int off = 16; off > 0; off >>= 1) acc += __shfl_xor_sync(0xffffffffu, acc, off);
    if (lane == 0) ws[wid] = acc;
    __syncthreads();
    if (k == 0) part[tkn] = ws[0] + ws[1] + ws[2] + ws[3];
}

__global__ void vq_reduce_k(const float* __restrict__ part, float* __restrict__ out_loss) {
    __shared__ float s[256];
    float a = 0.f;
    for (int i = threadIdx.x; i < BL_; i += 256) a += part[i];
    s[threadIdx.x] = a;
    __syncthreads();
    for (int st = 128; st > 0; st >>= 1) {
        if (threadIdx.x < st) s[threadIdx.x] += s[threadIdx.x + st];
        __syncthreads();
    }
    if (threadIdx.x == 0) out_loss[0] = 2.f * s[0] / (float)BLD_;
}

// ---------------- stack partial (gate recomputed) ----------------
__global__ void gate_stack_k(const float* __restrict__ G, const float* __restrict__ Cg,
                             const int* __restrict__ idx, float* __restrict__ part2) {
    int b = blockIdx.x, p = blockIdx.y, d = threadIdx.x;
    float cg = Cg[b * D_ + d];
    float s = 0.f;
    int tbase = b * L_ + p * 64;
#pragma unroll 4
    for (int l = 0; l < 64; l++) {
        int tok = tbase + l;
        float x = G[(long long)idx[tok] * D_ + d] + cg;
        s += 1.f / (1.f + __expf(-x));
    }
    part2[((long long)b * 8 + p) * D_ + d] = s;
}

// ln+modrelu over the (b, codebook) TABLE; reduces part2 inline; kcode==0 rows
// also write the stack_top output (identical add order).
__global__ void ln_tab_k(const float* __restrict__ G, const float* __restrict__ Cg,
                         const float* __restrict__ part2,
                         const float* __restrict__ lg, const float* __restrict__ lb,
                         const float* __restrict__ ib, const float* __restrict__ mb,
                         __half* __restrict__ Ytab16, float* __restrict__ out_stk) {
    int row = blockIdx.x;            // b*128 + k
    int b = row >> 7, kcode = row & 127;
    int d = threadIdx.x;
    int wid = d >> 5, lane = d & 31;
    __shared__ float ws1[8], ws2[8];
    float stk = 0.f;
#pragma unroll
    for (int p = 0; p < 8; p++) stk += part2[((long long)b * 8 + p) * D_ + d];
    if (kcode == 0) out_stk[b * D_ + d] = stk;
    float gx = G[(long long)kcode * D_ + d] + Cg[b * D_ + d];
    float x = 1.f / (1.f + __expf(-gx)) + stk;
    float s1 = x, s2 = x * x;
#pragma unroll
    for (int off = 16; off > 0; off >>= 1) {
        s1 += __shfl_xor_sync(0xffffffffu, s1, off);
        s2 += __shfl_xor_sync(0xffffffffu, s2, off);
    }
    if (lane == 0) { ws1[wid] = s1; ws2[wid] = s2; }
    __syncthreads();
    float t1 = 0.f, t2 = 0.f;
#pragma unroll
    for (int i = 0; i < 8; i++) { t1 += ws1[i]; t2 += ws2[i]; }
    float mu = t1 * (1.f / 256.f);
    float var = t2 * (1.f / 256.f) - mu * mu;
    float nr = (x - mu) * rsqrtf(var + 1e-5f) * lg[d] + lb[d];
    float ni = ib[d];
    float mag = sqrtf(nr * nr + ni * ni);
    float sc = fmaxf(mag + mb[d], 0.f) / (mag + 1e-6f);
    Ytab16[(long long)row * D_ + d] = __float2half(nr * sc);
}

// scatter logits table rows to tokens (streaming stores)
__global__ __launch_bounds__(256)
void scatter_k(const float* __restrict__ LT, const int* __restrict__ idx,
               float* __restrict__ out) {
    int tok = blockIdx.x;
    int b = tok >> 9;
    const float4* src = reinterpret_cast<const float4*>(
        LT + ((size_t)(b * KC_ + idx[tok]) << 12));
    float* dst = out + ((size_t)tok << 12);
    int t = threadIdx.x;
#pragma unroll
    for (int i = 0; i < 4; i++) {
        float4 v = src[t + i * 256];
        STG_CS_F4(dst + (t + i * 256) * 4, v);
    }
}

// ---------------- host launch ----------------
extern "C" void kernel_launch(void* const* d_in, const int* in_sizes, int n_in,
                              void* d_out, int out_size) {
    const int*   tokens = (const int*)d_in[0];
    const float* context = (const float*)d_in[1];
    const float* emb = (const float*)d_in[2];
    const float* awr = (const float*)d_in[3];
    const float* awi = (const float*)d_in[4];
    const float* abr = (const float*)d_in[5];
    const float* abi = (const float*)d_in[6];
    const float* vqe = (const float*)d_in[7];
    const float* gw  = (const float*)d_in[8];
    const float* gb  = (const float*)d_in[9];
    const float* lrg = (const float*)d_in[10];
    const float* lrb = (const float*)d_in[11];
    const float* lib = (const float*)d_in[13];
    const float* mrb = (const float*)d_in[14];
    const float* hw  = (const float*)d_in[15];
    const float* hb  = (const float*)d_in[16];
    float* out = (float*)d_out;

    float* S; cudaGetSymbolAddress((void**)&S, d_scratch);
    __nv_bfloat16* BF; cudaGetSymbolAddress((void**)&BF, d_bf);
    __half* HF; cudaGetSymbolAddress((void**)&HF, d_hf);
    int* idxb; cudaGetSymbolAddress((void**)&idxb, d_idxbuf);

    cudaFuncSetAttribute(gemmS<true>, cudaFuncAttributeMaxDynamicSharedMemorySize, GS_SMEM);
    cudaFuncSetAttribute((gemm1<0, false>), cudaFuncAttributeMaxDynamicSharedMemorySize, G1_SMEM);
    cudaFuncSetAttribute((gemm1<1, false>), cudaFuncAttributeMaxDynamicSharedMemorySize, G1_SMEM);
    cudaFuncSetAttribute((gemm1<2, true>),  cudaFuncAttributeMaxDynamicSharedMemorySize, G1_SMEM);
    cudaFuncSetAttribute(attn_mma, cudaFuncAttributeMaxDynamicSharedMemorySize, ATT_SMEM);

    float* DOT   = S + OFF_DOT;
    float* LT    = S + OFF_LT;
    float* G     = S + OFF_G;
    float* Cg    = S + OFF_CG;
    float* wev   = S + OFF_WEV;
    float* wct   = S + OFF_WCT;
    float* en    = S + OFF_EN;
    float* part  = S + OFF_PART;
    float* bqkv  = S + OFF_BQKV;
    float* bzr   = S + OFF_BZR;
    float* part2 = S + OFF_PART2;

    __nv_bfloat16* XBF  = BF + BF_X;
    __nv_bfloat16* WQBF = BF + BF_WQ;
    __nv_bfloat16* QKVB = BF + BF_QKV;
    __nv_bfloat16* APB  = BF + BF_AP;
    __nv_bfloat16* WZBF = BF + BF_WZ;

    __half* HW16 = HF + HF_HW;
    __half* Y16  = HF + HF_Y;
    __half* Z16  = HF + HF_Z;
    __half* VQ16 = HF + HF_VQ;

    prep_all_k<<<22920, 256>>>(abr, abi, gw, vqe, awr, awi, hw, tokens, emb,
                               bqkv, bzr, en, wev, wct,
                               WQBF, WZBF, VQ16, HW16, XBF);

    // QKV GEMM (128x128, 2 CTA/SM) -> bf16 packed QKV
    gemm1<0, false><<<dim3(1536 / 128, BL_ / 128), 256, G1_SMEM>>>(
        XBF, WQBF, bqkv, QKVB, nullptr, nullptr, 1536, 256);

    // flash attention (K/V resident per (b,h))
    attn_mma<<<B_ * H_, 256, ATT_SMEM>>>(QKVB, APB);

    // out clinear -> Z16 fp16 only
    gemm1<1, false><<<dim3(256 / 128, BL_ / 128), 256, G1_SMEM>>>(
        APB, WZBF, bzr, nullptr, Z16, nullptr, 256, 512);

    // VQ dot (fp16 inputs, 128x128 tiles, 2 CTA/SM -> full-chip single wave)
    gemm1<2, true><<<dim3(1, BL_ / 128), 256, G1_SMEM>>>(
        (const __nv_bfloat16*)Z16, (const __nv_bfloat16*)VQ16,
        nullptr, nullptr, nullptr, DOT, KC_, 256);
    vq_argmin_k<<<BL_, 128>>>(DOT, en, Z16, vqe, idxb, part);
    vq_reduce_k<<<1, 256>>>(part, out + BLV_);

    // gate tables (single launch)
    gate_tabs_k<<<dim3(2, 2), 256>>>(vqe, wev, context, wct, gb, G, Cg);

    // stack partials; ln_tab reduces part2 + writes stack_top output
    gate_stack_k<<<dim3(B_, 8), 256>>>(G, Cg, idxb, part2);
    ln_tab_k<<<NTAB, D_>>>(G, Cg, part2, lrg, lrb, lib, mrb, Y16, out + BLV_ + 1);

    // head GEMM on the table: LT (4096 x 4096) = Ytab @ hw^T + hb
    gemmS<true><<<dim3(V_ / 128, NTAB / 256), 512, GS_SMEM>>>(
        Y16, HW16, hb, LT, V_, 256);

    // scatter table rows to all tokens
    scatter_k<<<BL_, 256>>>(LT, idxb, out);
}